// round 3
// baseline (speedup 1.0000x reference)
#include <cuda_runtime.h>
#include <cstdint>

#define NN    4096
#define DF    128
#define DR    64
#define HID   1024
#define TOPK  10
#define XDIM  192   // DF + DR

// ---------------- static scratch (no runtime allocation allowed) ----------------
__device__ float g_key[(size_t)NN * NN];     // clamped d2 keys  (64 MB)
__device__ float g_x0 [NN * XDIM];           // concat(cond, tens)
__device__ float g_h1 [NN * HID];
__device__ float g_h2 [NN * HID];
__device__ float g_pushed[NN * DR];
__device__ float g_sq [NN];
__device__ int   g_nidx[NN * TOPK];

// ---------------- helpers ----------------
__device__ __forceinline__ float softplus_f(float x) {
    // matches jax.nn.softplus = max(x,0) + log1p(exp(-|x|))
    return fmaxf(x, 0.0f) + log1pf(expf(-fabsf(x)));
}

__device__ __forceinline__ unsigned long long pack2(float a, float b) {
    unsigned long long r;
    asm("mov.b64 %0, {%1, %2};" : "=l"(r) : "f"(a), "f"(b));
    return r;
}
__device__ __forceinline__ void unpack2(unsigned long long v, float& a, float& b) {
    asm("mov.b64 {%0, %1}, %2;" : "=f"(a), "=f"(b) : "l"(v));
}
__device__ __forceinline__ void fma2(unsigned long long& d, unsigned long long a, unsigned long long b) {
    asm("fma.rn.f32x2 %0, %1, %2, %0;" : "+l"(d) : "l"(a), "l"(b));
}

// ---------------- sq[i] = sum(condition[i]^2) : one warp per row ----------------
__global__ void sq_kernel(const float* __restrict__ cond, float* __restrict__ sq) {
    const int row  = blockIdx.x * 8 + (threadIdx.x >> 5);
    const int lane = threadIdx.x & 31;
    const float4 t = reinterpret_cast<const float4*>(cond)[row * 32 + lane]; // 128 f = 32 f4
    float s = t.x * t.x + t.y * t.y + t.z * t.z + t.w * t.w;
    #pragma unroll
    for (int o = 16; o > 0; o >>= 1) s += __shfl_down_sync(0xffffffffu, s, o);
    if (lane == 0) sq[row] = s;
}

// ---------------- x0 = concat(cond, tens) per row ----------------
__global__ void concat_kernel(const float* __restrict__ cond, const float* __restrict__ tens,
                              float* __restrict__ x0) {
    const int idx = blockIdx.x * blockDim.x + threadIdx.x;   // over NN*48 float4
    if (idx >= NN * 48) return;
    const int r = idx / 48, c = idx % 48;
    const float4* c4 = reinterpret_cast<const float4*>(cond);
    const float4* t4 = reinterpret_cast<const float4*>(tens);
    float4 v = (c < 32) ? c4[r * 32 + c] : t4[r * 16 + (c - 32)];
    reinterpret_cast<float4*>(x0)[idx] = v;
}

// ---------------- generic fp32 GEMM (f32x2 packed FMA), fused epilogues ----------
// C[M,N] = A[M,K] @ B      (TRB=false: B is [K,N] row-major;  TRB=true: B is [N,K] row-major)
// EPI 0: softplus(acc + bias[c])
// EPI 1: extra[r,c] - (acc + bias[c])
// EPI 2: max(bias[r] + bias[c] - 2*acc, 0)          (gram -> clamped d2 key; bias = sq)
template<int BM, int BN, int BK, int TM, int TN, int EPI, bool TRB>
__global__ void __launch_bounds__((BM / TM) * (BN / TN))
gemm_k(const float* __restrict__ A, const float* __restrict__ B,
       const float* __restrict__ bias, const float* __restrict__ extra,
       float* __restrict__ C, int M, int N, int K)
{
    constexpr int THREADS = (BM / TM) * (BN / TN);
    constexpr int TN2 = TN / 2;
    __shared__ float As[BK][BM];
    __shared__ float Bs[BK][BN];

    const int tid  = threadIdx.x;
    const int tx   = tid % (BN / TN);
    const int ty   = tid / (BN / TN);
    const int row0 = blockIdx.y * BM;
    const int col0 = blockIdx.x * BN;

    unsigned long long acc[TM][TN2];
    #pragma unroll
    for (int i = 0; i < TM; i++)
        #pragma unroll
        for (int j = 0; j < TN2; j++) acc[i][j] = 0ull;

    for (int kt = 0; kt < K; kt += BK) {
        // A tile -> As (transposed for contiguous m)
        #pragma unroll
        for (int f = tid; f < BM * BK / 4; f += THREADS) {
            const int m = f / (BK / 4);
            const int k = (f % (BK / 4)) * 4;
            const float4 t = *reinterpret_cast<const float4*>(A + (size_t)(row0 + m) * K + kt + k);
            As[k + 0][m] = t.x; As[k + 1][m] = t.y; As[k + 2][m] = t.z; As[k + 3][m] = t.w;
        }
        if (TRB) {
            #pragma unroll
            for (int f = tid; f < BN * BK / 4; f += THREADS) {
                const int n = f / (BK / 4);
                const int k = (f % (BK / 4)) * 4;
                const float4 t = *reinterpret_cast<const float4*>(B + (size_t)(col0 + n) * K + kt + k);
                Bs[k + 0][n] = t.x; Bs[k + 1][n] = t.y; Bs[k + 2][n] = t.z; Bs[k + 3][n] = t.w;
            }
        } else {
            #pragma unroll
            for (int f = tid; f < BK * BN / 4; f += THREADS) {
                const int k = f / (BN / 4);
                const int n = (f % (BN / 4)) * 4;
                *reinterpret_cast<float4*>(&Bs[k][n]) =
                    *reinterpret_cast<const float4*>(B + (size_t)(kt + k) * N + col0 + n);
            }
        }
        __syncthreads();

        #pragma unroll
        for (int kk = 0; kk < BK; kk++) {
            float ra[TM];
            #pragma unroll
            for (int i = 0; i < TM; i++) ra[i] = As[kk][ty * TM + i];
            unsigned long long rb[TN2];
            const unsigned long long* bsp =
                reinterpret_cast<const unsigned long long*>(&Bs[kk][tx * TN]);
            #pragma unroll
            for (int j = 0; j < TN2; j++) rb[j] = bsp[j];
            #pragma unroll
            for (int i = 0; i < TM; i++) {
                const unsigned long long a2 = pack2(ra[i], ra[i]);
                #pragma unroll
                for (int j = 0; j < TN2; j++) fma2(acc[i][j], a2, rb[j]);
            }
        }
        __syncthreads();
    }

    #pragma unroll
    for (int i = 0; i < TM; i++) {
        const int r = row0 + ty * TM + i;
        #pragma unroll
        for (int j = 0; j < TN2; j++) {
            float v0, v1;
            unpack2(acc[i][j], v0, v1);
            const int c = col0 + tx * TN + 2 * j;
            float o0, o1;
            if constexpr (EPI == 0) {
                o0 = softplus_f(v0 + bias[c]);
                o1 = softplus_f(v1 + bias[c + 1]);
            } else if constexpr (EPI == 1) {
                o0 = extra[(size_t)r * N + c]     - (v0 + bias[c]);
                o1 = extra[(size_t)r * N + c + 1] - (v1 + bias[c + 1]);
            } else {
                const float si = bias[r];
                o0 = fmaxf(si + bias[c]     - 2.0f * v0, 0.0f);
                o1 = fmaxf(si + bias[c + 1] - 2.0f * v1, 0.0f);
            }
            C[(size_t)r * N + c]     = o0;
            C[(size_t)r * N + c + 1] = o1;
        }
    }
}

// ---------------- top-10 smallest per row (1 warp / row), ties -> lower index -----
__global__ void topk_kernel(const float* __restrict__ key, int* __restrict__ out_idx) {
    const int row  = blockIdx.x * 8 + (threadIdx.x >> 5);
    const int lane = threadIdx.x & 31;
    const float* krow = key + (size_t)row * NN;

    float v[TOPK];
    int   id[TOPK];
    #pragma unroll
    for (int t = 0; t < TOPK; t++) { v[t] = 3.0e38f; id[t] = 0x7fffffff; }

    // per-lane sorted insertion (j ascending within a lane => within-lane tie-break is automatic)
    for (int j = lane; j < NN; j += 32) {
        const float x = krow[j];
        if (x < v[TOPK - 1]) {
            int p = TOPK - 1;
            while (p > 0 && x < v[p - 1]) { v[p] = v[p - 1]; id[p] = id[p - 1]; --p; }
            v[p] = x; id[p] = j;
        }
    }

    // 32-way sorted-list merge via warp shuffles; comparator (value asc, index asc)
    int head = 0;
    #pragma unroll
    for (int k = 0; k < TOPK; k++) {
        float mv = 3.0e38f; int mi = 0x7fffffff;
        if (head < TOPK) { mv = v[head]; mi = id[head]; }
        #pragma unroll
        for (int off = 16; off > 0; off >>= 1) {
            const float ov = __shfl_down_sync(0xffffffffu, mv, off);
            const int   oi = __shfl_down_sync(0xffffffffu, mi, off);
            if (ov < mv || (ov == mv && oi < mi)) { mv = ov; mi = oi; }
        }
        mv = __shfl_sync(0xffffffffu, mv, 0);
        mi = __shfl_sync(0xffffffffu, mi, 0);
        if (head < TOPK && id[head] == mi) head++;   // advance winning lane (idx unique per lane)
        if (lane == 0) out_idx[row * TOPK + k] = mi;
    }
}

// ---------------- final gather: out[i,k,:] = pushed[nidx[i,k], :] ----------------
__global__ void gather_kernel(const int* __restrict__ nidx, const float* __restrict__ pushed,
                              float* __restrict__ out) {
    const int t = blockIdx.x * blockDim.x + threadIdx.x;   // over NN*TOPK*16 float4
    if (t >= NN * TOPK * 16) return;
    const int r = t >> 4, c = t & 15;
    const int j = nidx[r];
    reinterpret_cast<float4*>(out)[t] =
        reinterpret_cast<const float4*>(pushed)[j * 16 + c];
}

// ---------------- launch ----------------
extern "C" void kernel_launch(void* const* d_in, const int* in_sizes, int n_in,
                              void* d_out, int out_size)
{
    const float* cond = (const float*)d_in[0];
    const float* tens = (const float*)d_in[1];
    const float* Win  = (const float*)d_in[2];
    const float* b_in = (const float*)d_in[3];
    const float* W1   = (const float*)d_in[4];
    const float* b1   = (const float*)d_in[5];
    const float* W2   = (const float*)d_in[6];
    const float* b2   = (const float*)d_in[7];
    const float* W3   = (const float*)d_in[8];
    const float* b3   = (const float*)d_in[9];
    const float* Wout = (const float*)d_in[10];
    const float* bout = (const float*)d_in[11];
    float* out = (float*)d_out;

    float *key, *x0, *h1, *h2, *pushed, *sq;
    int*   nidx;
    cudaGetSymbolAddress((void**)&key,    g_key);
    cudaGetSymbolAddress((void**)&x0,     g_x0);
    cudaGetSymbolAddress((void**)&h1,     g_h1);
    cudaGetSymbolAddress((void**)&h2,     g_h2);
    cudaGetSymbolAddress((void**)&pushed, g_pushed);
    cudaGetSymbolAddress((void**)&sq,     g_sq);
    cudaGetSymbolAddress((void**)&nidx,   g_nidx);

    // 1. row squared norms
    sq_kernel<<<NN / 8, 256>>>(cond, sq);

    // 2. MLP input rows (one per unique point)
    concat_kernel<<<(NN * 48 + 255) / 256, 256>>>(cond, tens, x0);

    // 3. gram -> clamped d2 keys (GEMM-NT, fused epilogue)
    gemm_k<128, 128, 16, 8, 8, 2, true><<<dim3(NN / 128, NN / 128), 256>>>(
        cond, cond, sq, nullptr, key, NN, NN, DF);

    // 4. top-10 neighbor indices per row
    topk_kernel<<<NN / 8, 256>>>(key, nidx);

    // 5. MLP over the 4096 unique rows (fused bias + softplus)
    gemm_k<128, 128, 16, 8, 8, 0, false><<<dim3(HID / 128, NN / 128), 256>>>(
        x0, Win, b_in, nullptr, h1, NN, HID, XDIM);
    gemm_k<128, 128, 16, 8, 8, 0, false><<<dim3(HID / 128, NN / 128), 256>>>(
        h1, W1, b1, nullptr, h2, NN, HID, HID);
    gemm_k<128, 128, 16, 8, 8, 0, false><<<dim3(HID / 128, NN / 128), 256>>>(
        h2, W2, b2, nullptr, h1, NN, HID, HID);
    gemm_k<128, 128, 16, 8, 8, 0, false><<<dim3(HID / 128, NN / 128), 256>>>(
        h1, W3, b3, nullptr, h2, NN, HID, HID);

    // 6. output layer fused with pushforward: pushed = tensor - (h @ Wout + b_out)
    gemm_k<32, 64, 16, 2, 8, 1, false><<<dim3(DR / 64, NN / 32), 128>>>(
        h2, Wout, bout, tens, pushed, NN, DR, HID);

    // 7. gather the 40960 output rows
    gather_kernel<<<(NN * TOPK * 16 + 255) / 256, 256>>>(nidx, pushed, out);
}

// round 5
// speedup vs baseline: 2.3880x; 2.3880x over previous
#include <cuda_runtime.h>
#include <cuda_fp16.h>
#include <cstdint>

#define NN    4096
#define DF    128
#define DR    64
#define HID   1024
#define TOPK  10
#define XDIM  192

typedef __half f16;

// ---------------- static scratch ----------------
__device__ float g_key[(size_t)NN * NN];
__device__ float g_sq [NN];
__device__ int   g_nidx[NN * TOPK];
__device__ float g_pushed[NN * DR];

__device__ f16 g_x0h[NN * XDIM], g_x0l[NN * XDIM];
__device__ f16 g_hAh[NN * HID],  g_hAl[NN * HID];
__device__ f16 g_hBh[NN * HID],  g_hBl[NN * HID];
__device__ f16 g_Wih[XDIM * HID], g_Wil[XDIM * HID];
__device__ f16 g_W1h[HID * HID],  g_W1l[HID * HID];
__device__ f16 g_W2h[HID * HID],  g_W2l[HID * HID];
__device__ f16 g_W3h[HID * HID],  g_W3l[HID * HID];
__device__ f16 g_Woh[HID * DR],   g_Wol[HID * DR];

// ---------------- helpers ----------------
__device__ __forceinline__ float sp(float x) {
    return fmaxf(x, 0.0f) + log1pf(expf(-fabsf(x)));
}

__device__ __forceinline__ void cpa16(void* s, const void* g) {
    uint32_t sa = (uint32_t)__cvta_generic_to_shared(s);
    asm volatile("cp.async.cg.shared.global [%0], [%1], 16;" :: "r"(sa), "l"(g) : "memory");
}
#define CP_COMMIT() asm volatile("cp.async.commit_group;" ::: "memory")
#define CP_WAIT1()  asm volatile("cp.async.wait_group 1;" ::: "memory")

__device__ __forceinline__ void ldm_x4(uint32_t* r, const void* p) {
    uint32_t a = (uint32_t)__cvta_generic_to_shared(p);
    asm volatile("ldmatrix.sync.aligned.m8n8.x4.shared.b16 {%0,%1,%2,%3}, [%4];"
        : "=r"(r[0]), "=r"(r[1]), "=r"(r[2]), "=r"(r[3]) : "r"(a));
}
__device__ __forceinline__ void ldm_x2t(uint32_t* r, const void* p) {
    uint32_t a = (uint32_t)__cvta_generic_to_shared(p);
    asm volatile("ldmatrix.sync.aligned.m8n8.x2.trans.shared.b16 {%0,%1}, [%2];"
        : "=r"(r[0]), "=r"(r[1]) : "r"(a));
}
__device__ __forceinline__ void mma16816(float* c, const uint32_t* a, const uint32_t* b) {
    asm volatile("mma.sync.aligned.m16n8k16.row.col.f32.f16.f16.f32 "
        "{%0,%1,%2,%3}, {%4,%5,%6,%7}, {%8,%9}, {%0,%1,%2,%3};"
        : "+f"(c[0]), "+f"(c[1]), "+f"(c[2]), "+f"(c[3])
        : "r"(a[0]), "r"(a[1]), "r"(a[2]), "r"(a[3]), "r"(b[0]), "r"(b[1]));
}

__device__ __forceinline__ void split1(float v, f16& h, f16& l) {
    h = __float2half(v);
    l = __float2half(v - __half2float(h));
}

__device__ __forceinline__ unsigned long long pack2f(float a, float b) {
    unsigned long long r;
    asm("mov.b64 %0, {%1, %2};" : "=l"(r) : "f"(a), "f"(b));
    return r;
}
__device__ __forceinline__ void unpack2f(unsigned long long v, float& a, float& b) {
    asm("mov.b64 {%0, %1}, %2;" : "=f"(a), "=f"(b) : "l"(v));
}
__device__ __forceinline__ void fma2(unsigned long long& d, unsigned long long a, unsigned long long b) {
    asm("fma.rn.f32x2 %0, %1, %2, %0;" : "+l"(d) : "l"(a), "l"(b));
}

// ---------------- small prep kernels ----------------
__global__ void sq_kernel(const float* __restrict__ cond, float* __restrict__ sq) {
    const int row  = blockIdx.x * 8 + (threadIdx.x >> 5);
    const int lane = threadIdx.x & 31;
    const float4 t = reinterpret_cast<const float4*>(cond)[row * 32 + lane];
    float s = t.x * t.x + t.y * t.y + t.z * t.z + t.w * t.w;
    #pragma unroll
    for (int o = 16; o > 0; o >>= 1) s += __shfl_down_sync(0xffffffffu, s, o);
    if (lane == 0) sq[row] = s;
}

__global__ void split_kernel(const float* __restrict__ src, f16* __restrict__ hi,
                             f16* __restrict__ lo, int n) {
    const int i = blockIdx.x * blockDim.x + threadIdx.x;
    if (i >= n) return;
    f16 h, l; split1(src[i], h, l);
    hi[i] = h; lo[i] = l;
}

// x0 = concat(cond, tens), split
__global__ void concat_split_kernel(const float* __restrict__ cond, const float* __restrict__ tens,
                                    f16* __restrict__ hi, f16* __restrict__ lo) {
    const int i = blockIdx.x * blockDim.x + threadIdx.x;
    if (i >= NN * XDIM) return;
    const int r = i / XDIM, c = i % XDIM;
    const float v = (c < DF) ? cond[r * DF + c] : tens[r * DR + (c - DF)];
    f16 h, l; split1(v, h, l);
    hi[i] = h; lo[i] = l;
}

// ---------------- exact fp32 SIMT gram kernel (proven in round 2) ----------------
// key[r][c] = max(sq[r] + sq[c] - 2 * dot(cond[r], cond[c]), 0)
__global__ void __launch_bounds__(256)
gram_kernel(const float* __restrict__ A, const float* __restrict__ sq,
            float* __restrict__ C)
{
    constexpr int BM = 128, BN = 128, BK = 16, TM = 8, TN = 8;
    constexpr int THREADS = 256;
    constexpr int TN2 = TN / 2;
    __shared__ float As[BK][BM];
    __shared__ float Bs[BK][BN];

    const int tid  = threadIdx.x;
    const int tx   = tid % (BN / TN);
    const int ty   = tid / (BN / TN);
    const int row0 = blockIdx.y * BM;
    const int col0 = blockIdx.x * BN;

    unsigned long long acc[TM][TN2];
    #pragma unroll
    for (int i = 0; i < TM; i++)
        #pragma unroll
        for (int j = 0; j < TN2; j++) acc[i][j] = 0ull;

    for (int kt = 0; kt < DF; kt += BK) {
        #pragma unroll
        for (int f = tid; f < BM * BK / 4; f += THREADS) {
            const int m = f / (BK / 4);
            const int k = (f % (BK / 4)) * 4;
            const float4 t = *reinterpret_cast<const float4*>(A + (size_t)(row0 + m) * DF + kt + k);
            As[k + 0][m] = t.x; As[k + 1][m] = t.y; As[k + 2][m] = t.z; As[k + 3][m] = t.w;
        }
        #pragma unroll
        for (int f = tid; f < BN * BK / 4; f += THREADS) {
            const int n = f / (BK / 4);
            const int k = (f % (BK / 4)) * 4;
            const float4 t = *reinterpret_cast<const float4*>(A + (size_t)(col0 + n) * DF + kt + k);
            Bs[k + 0][n] = t.x; Bs[k + 1][n] = t.y; Bs[k + 2][n] = t.z; Bs[k + 3][n] = t.w;
        }
        __syncthreads();

        #pragma unroll
        for (int kk = 0; kk < BK; kk++) {
            float ra[TM];
            #pragma unroll
            for (int i = 0; i < TM; i++) ra[i] = As[kk][ty * TM + i];
            unsigned long long rb[TN2];
            const unsigned long long* bsp =
                reinterpret_cast<const unsigned long long*>(&Bs[kk][tx * TN]);
            #pragma unroll
            for (int j = 0; j < TN2; j++) rb[j] = bsp[j];
            #pragma unroll
            for (int i = 0; i < TM; i++) {
                const unsigned long long a2 = pack2f(ra[i], ra[i]);
                #pragma unroll
                for (int j = 0; j < TN2; j++) fma2(acc[i][j], a2, rb[j]);
            }
        }
        __syncthreads();
    }

    #pragma unroll
    for (int i = 0; i < TM; i++) {
        const int r = row0 + ty * TM + i;
        const float sr = sq[r];
        #pragma unroll
        for (int j = 0; j < TN2; j++) {
            float v0, v1;
            unpack2f(acc[i][j], v0, v1);
            const int c = col0 + tx * TN + 2 * j;
            C[(size_t)r * NN + c]     = fmaxf(sr + sq[c]     - 2.0f * v0, 0.0f);
            C[(size_t)r * NN + c + 1] = fmaxf(sr + sq[c + 1] - 2.0f * v1, 0.0f);
        }
    }
}

// ---------------- split-fp16 tensor-core GEMM (MLP layers) ----------------
// C[M,N] ~= (Ah+Al)@(Bh+Bl)  (drop lo*lo).  BM=128, BK=16, warp tile 64x32.
// EPI 0: y = softplus(acc + bias[c]) -> write split fp16 (Oh, Ol)
// EPI 1: Cf = extra - (acc + bias[c])
template<int BN, int EPI>
__global__ void __launch_bounds__((BN / 32) * 64)
mma_gemm(const f16* __restrict__ Ah, const f16* __restrict__ Al,
         const f16* __restrict__ Bh, const f16* __restrict__ Bl,
         const float* __restrict__ bias, const float* __restrict__ extra,
         float* __restrict__ Cf, f16* __restrict__ Oh, f16* __restrict__ Ol,
         int M, int N, int K)
{
    constexpr int WN = BN / 32;
    constexpr int THREADS = 2 * WN * 32;
    constexpr int AST = 24;       // As row stride: 48B, conflict-free ldmatrix
    constexpr int BST = BN + 8;   // Bs row stride

    __shared__ __align__(16) f16 As[2][2][128 * AST];
    __shared__ __align__(16) f16 Bs[2][2][16 * BST];

    const int tid  = threadIdx.x;
    const int lane = tid & 31;
    const int w    = tid >> 5;
    const int wm   = w / WN;
    const int wn   = w % WN;
    const int row0 = blockIdx.y * 128;
    const int col0 = blockIdx.x * BN;

    float acc[4][4][4];
    #pragma unroll
    for (int a = 0; a < 4; a++)
        #pragma unroll
        for (int b = 0; b < 4; b++)
            #pragma unroll
            for (int c = 0; c < 4; c++) acc[a][b][c] = 0.0f;

    const int nchunk = K / 16;

    auto load_chunk = [&](int ci, int buf) {
        const int kt = ci * 16;
        #pragma unroll
        for (int s = 0; s < 2; s++) {
            const f16* Ag = s ? Al : Ah;
            for (int f = tid; f < 128 * 2; f += THREADS) {
                const int m = f >> 1, c = (f & 1) * 8;
                cpa16(&As[buf][s][m * AST + c], Ag + (size_t)(row0 + m) * K + kt + c);
            }
            const f16* Bg = s ? Bl : Bh;
            for (int f = tid; f < 16 * (BN / 8); f += THREADS) {
                const int k = f / (BN / 8), c = (f % (BN / 8)) * 8;
                cpa16(&Bs[buf][s][k * BST + c], Bg + (size_t)(kt + k) * N + col0 + c);
            }
        }
    };

    load_chunk(0, 0);
    CP_COMMIT();

    for (int ci = 0; ci < nchunk; ci++) {
        const int buf = ci & 1;
        if (ci + 1 < nchunk) load_chunk(ci + 1, buf ^ 1);
        CP_COMMIT();
        CP_WAIT1();
        __syncthreads();

        uint32_t a[4][4], b[4][2];
        const int arow = wm * 64 + (lane & 15);
        const int acol = (lane >> 4) << 3;
        const int brow = (lane & 15) * BST;
        const int bcol = wn * 32;

        // pass 1: Ahi x Blo
        #pragma unroll
        for (int mt = 0; mt < 4; mt++)
            ldm_x4(a[mt], &As[buf][0][(arow + mt * 16) * AST + acol]);
        #pragma unroll
        for (int nt = 0; nt < 4; nt++)
            ldm_x2t(b[nt], &Bs[buf][1][brow + bcol + nt * 8]);
        #pragma unroll
        for (int mt = 0; mt < 4; mt++)
            #pragma unroll
            for (int nt = 0; nt < 4; nt++) mma16816(acc[mt][nt], a[mt], b[nt]);

        // pass 2: Ahi x Bhi
        #pragma unroll
        for (int nt = 0; nt < 4; nt++)
            ldm_x2t(b[nt], &Bs[buf][0][brow + bcol + nt * 8]);
        #pragma unroll
        for (int mt = 0; mt < 4; mt++)
            #pragma unroll
            for (int nt = 0; nt < 4; nt++) mma16816(acc[mt][nt], a[mt], b[nt]);

        // pass 3: Alo x Bhi (b regs reused)
        #pragma unroll
        for (int mt = 0; mt < 4; mt++)
            ldm_x4(a[mt], &As[buf][1][(arow + mt * 16) * AST + acol]);
        #pragma unroll
        for (int mt = 0; mt < 4; mt++)
            #pragma unroll
            for (int nt = 0; nt < 4; nt++) mma16816(acc[mt][nt], a[mt], b[nt]);

        __syncthreads();
    }

    // epilogue
    #pragma unroll
    for (int mt = 0; mt < 4; mt++) {
        #pragma unroll
        for (int nt = 0; nt < 4; nt++) {
            const int r = row0 + wm * 64 + mt * 16 + (lane >> 2);
            const int c = col0 + wn * 32 + nt * 8 + ((lane & 3) << 1);
            const float* ac = acc[mt][nt];
            if constexpr (EPI == 0) {
                const float bc0 = bias[c], bc1 = bias[c + 1];
                #pragma unroll
                for (int h = 0; h < 2; h++) {
                    const int rr = r + 8 * h;
                    const float y0 = sp(ac[2 * h] + bc0);
                    const float y1 = sp(ac[2 * h + 1] + bc1);
                    f16 h0, l0, h1, l1;
                    split1(y0, h0, l0); split1(y1, h1, l1);
                    *(__half2*)(Oh + (size_t)rr * N + c) = __halves2half2(h0, h1);
                    *(__half2*)(Ol + (size_t)rr * N + c) = __halves2half2(l0, l1);
                }
            } else {
                const float bc0 = bias[c], bc1 = bias[c + 1];
                #pragma unroll
                for (int h = 0; h < 2; h++) {
                    const size_t o = (size_t)(r + 8 * h) * N + c;
                    Cf[o]     = extra[o]     - (ac[2 * h]     + bc0);
                    Cf[o + 1] = extra[o + 1] - (ac[2 * h + 1] + bc1);
                }
            }
        }
    }
}

// ---------------- top-10 smallest per row, all-register lists ----------------
__device__ __forceinline__ void ins10(float x, int j, float (&v)[TOPK], int (&id)[TOPK]) {
    if (x >= v[TOPK - 1]) return;
    #pragma unroll
    for (int t = TOPK - 1; t > 0; t--) {
        const bool shf = (x < v[t - 1]);
        const bool put = !shf && (x < v[t]);
        v[t]  = shf ? v[t - 1]  : (put ? x : v[t]);
        id[t] = shf ? id[t - 1] : (put ? j : id[t]);
    }
    if (x < v[0]) { v[0] = x; id[0] = j; }
}

__global__ void topk_kernel(const float* __restrict__ key, int* __restrict__ out_idx) {
    const int row  = blockIdx.x * 8 + (threadIdx.x >> 5);
    const int lane = threadIdx.x & 31;
    const float4* k4 = reinterpret_cast<const float4*>(key + (size_t)row * NN);

    float v[TOPK]; int id[TOPK];
    #pragma unroll
    for (int t = 0; t < TOPK; t++) { v[t] = 3.0e38f; id[t] = 0x7fffffff; }

    #pragma unroll 4
    for (int j = lane; j < NN / 4; j += 32) {
        const float4 t = k4[j];
        const int b = 4 * j;
        ins10(t.x, b,     v, id);
        ins10(t.y, b + 1, v, id);
        ins10(t.z, b + 2, v, id);
        ins10(t.w, b + 3, v, id);
    }

    #pragma unroll
    for (int k = 0; k < TOPK; k++) {
        float mv = v[0]; int mi = id[0];
        #pragma unroll
        for (int off = 16; off > 0; off >>= 1) {
            const float ov = __shfl_down_sync(0xffffffffu, mv, off);
            const int   oi = __shfl_down_sync(0xffffffffu, mi, off);
            if (ov < mv || (ov == mv && oi < mi)) { mv = ov; mi = oi; }
        }
        mv = __shfl_sync(0xffffffffu, mv, 0);
        mi = __shfl_sync(0xffffffffu, mi, 0);
        if (id[0] == mi) {
            #pragma unroll
            for (int t = 0; t < TOPK - 1; t++) { v[t] = v[t + 1]; id[t] = id[t + 1]; }
            v[TOPK - 1] = 3.0e38f; id[TOPK - 1] = 0x7fffffff;
        }
        if (lane == 0) out_idx[row * TOPK + k] = mi;
    }
}

// ---------------- final gather ----------------
__global__ void gather_kernel(const int* __restrict__ nidx, const float* __restrict__ pushed,
                              float* __restrict__ out) {
    const int t = blockIdx.x * blockDim.x + threadIdx.x;
    if (t >= NN * TOPK * 16) return;
    const int r = t >> 4, c = t & 15;
    const int j = nidx[r];
    reinterpret_cast<float4*>(out)[t] = reinterpret_cast<const float4*>(pushed)[j * 16 + c];
}

// ---------------- launch ----------------
extern "C" void kernel_launch(void* const* d_in, const int* in_sizes, int n_in,
                              void* d_out, int out_size)
{
    const float* cond = (const float*)d_in[0];
    const float* tens = (const float*)d_in[1];
    const float* Win  = (const float*)d_in[2];
    const float* b_in = (const float*)d_in[3];
    const float* W1   = (const float*)d_in[4];
    const float* b1   = (const float*)d_in[5];
    const float* W2   = (const float*)d_in[6];
    const float* b2   = (const float*)d_in[7];
    const float* W3   = (const float*)d_in[8];
    const float* b3   = (const float*)d_in[9];
    const float* Wout = (const float*)d_in[10];
    const float* bout = (const float*)d_in[11];
    float* out = (float*)d_out;

    float *key, *sq, *pushed; int* nidx;
    f16 *x0h, *x0l, *hAh, *hAl, *hBh, *hBl;
    f16 *Wih, *Wil, *W1h, *W1l, *W2h, *W2l, *W3h, *W3l, *Woh, *Wol;
    cudaGetSymbolAddress((void**)&key, g_key);
    cudaGetSymbolAddress((void**)&sq, g_sq);
    cudaGetSymbolAddress((void**)&nidx, g_nidx);
    cudaGetSymbolAddress((void**)&pushed, g_pushed);
    cudaGetSymbolAddress((void**)&x0h, g_x0h); cudaGetSymbolAddress((void**)&x0l, g_x0l);
    cudaGetSymbolAddress((void**)&hAh, g_hAh); cudaGetSymbolAddress((void**)&hAl, g_hAl);
    cudaGetSymbolAddress((void**)&hBh, g_hBh); cudaGetSymbolAddress((void**)&hBl, g_hBl);
    cudaGetSymbolAddress((void**)&Wih, g_Wih); cudaGetSymbolAddress((void**)&Wil, g_Wil);
    cudaGetSymbolAddress((void**)&W1h, g_W1h); cudaGetSymbolAddress((void**)&W1l, g_W1l);
    cudaGetSymbolAddress((void**)&W2h, g_W2h); cudaGetSymbolAddress((void**)&W2l, g_W2l);
    cudaGetSymbolAddress((void**)&W3h, g_W3h); cudaGetSymbolAddress((void**)&W3l, g_W3l);
    cudaGetSymbolAddress((void**)&Woh, g_Woh); cudaGetSymbolAddress((void**)&Wol, g_Wol);

    // prep
    sq_kernel<<<NN / 8, 256>>>(cond, sq);
    concat_split_kernel<<<(NN * XDIM + 255) / 256, 256>>>(cond, tens, x0h, x0l);
    split_kernel<<<(XDIM * HID + 255) / 256, 256>>>(Win, Wih, Wil, XDIM * HID);
    split_kernel<<<(HID * HID + 255) / 256, 256>>>(W1, W1h, W1l, HID * HID);
    split_kernel<<<(HID * HID + 255) / 256, 256>>>(W2, W2h, W2l, HID * HID);
    split_kernel<<<(HID * HID + 255) / 256, 256>>>(W3, W3h, W3l, HID * HID);
    split_kernel<<<(HID * DR + 255) / 256, 256>>>(Wout, Woh, Wol, HID * DR);

    // exact fp32 gram -> clamped d2 keys
    gram_kernel<<<dim3(NN / 128, NN / 128), 256>>>(cond, sq, key);

    // top-10 neighbors
    topk_kernel<<<NN / 8, 256>>>(key, nidx);

    // MLP over 4096 unique rows (split-fp16 tensor cores)
    mma_gemm<128, 0><<<dim3(HID / 128, NN / 128), 256>>>(
        x0h, x0l, Wih, Wil, b_in, nullptr, nullptr, hAh, hAl, NN, HID, XDIM);
    mma_gemm<128, 0><<<dim3(HID / 128, NN / 128), 256>>>(
        hAh, hAl, W1h, W1l, b1, nullptr, nullptr, hBh, hBl, NN, HID, HID);
    mma_gemm<128, 0><<<dim3(HID / 128, NN / 128), 256>>>(
        hBh, hBl, W2h, W2l, b2, nullptr, nullptr, hAh, hAl, NN, HID, HID);
    mma_gemm<128, 0><<<dim3(HID / 128, NN / 128), 256>>>(
        hAh, hAl, W3h, W3l, b3, nullptr, nullptr, hBh, hBl, NN, HID, HID);

    // output layer fused with pushforward
    mma_gemm<64, 1><<<dim3(DR / 64, NN / 128), 128>>>(
        hBh, hBl, Woh, Wol, bout, tens, pushed, nullptr, nullptr, NN, DR, HID);

    // gather
    gather_kernel<<<(NN * TOPK * 16 + 255) / 256, 256>>>(nidx, pushed, out);
}

// round 6
// speedup vs baseline: 2.5423x; 1.0646x over previous
#include <cuda_runtime.h>
#include <cuda_fp16.h>
#include <cstdint>

#define NN    4096
#define DF    128
#define DR    64
#define HID   1024
#define TOPK  10
#define NCAND 16
#define XDIM  192

typedef __half f16;

// ---------------- static scratch ----------------
__device__ float g_key[(size_t)NN * NN];
__device__ float g_sq [NN];
__device__ int   g_cand[NN * NCAND];
__device__ int   g_nidx[NN * TOPK];
__device__ float g_pushed[NN * DR];

__device__ f16 g_x0h[NN * XDIM], g_x0l[NN * XDIM];
__device__ f16 g_hAh[NN * HID],  g_hAl[NN * HID];
__device__ f16 g_hBh[NN * HID],  g_hBl[NN * HID];
__device__ f16 g_ch [NN * DF],   g_cl [NN * DF];
__device__ f16 g_cth[DF * NN],   g_ctl[DF * NN];
__device__ f16 g_Wih[XDIM * HID], g_Wil[XDIM * HID];
__device__ f16 g_W1h[HID * HID],  g_W1l[HID * HID];
__device__ f16 g_W2h[HID * HID],  g_W2l[HID * HID];
__device__ f16 g_W3h[HID * HID],  g_W3l[HID * HID];
__device__ f16 g_Woh[HID * DR],   g_Wol[HID * DR];

// ---------------- helpers ----------------
__device__ __forceinline__ float sp(float x) {
    return fmaxf(x, 0.0f) + log1pf(expf(-fabsf(x)));
}

__device__ __forceinline__ void cpa16(void* s, const void* g) {
    uint32_t sa = (uint32_t)__cvta_generic_to_shared(s);
    asm volatile("cp.async.cg.shared.global [%0], [%1], 16;" :: "r"(sa), "l"(g) : "memory");
}
#define CP_COMMIT() asm volatile("cp.async.commit_group;" ::: "memory")
#define CP_WAIT1()  asm volatile("cp.async.wait_group 1;" ::: "memory")

__device__ __forceinline__ void ldm_x4(uint32_t* r, const void* p) {
    uint32_t a = (uint32_t)__cvta_generic_to_shared(p);
    asm volatile("ldmatrix.sync.aligned.m8n8.x4.shared.b16 {%0,%1,%2,%3}, [%4];"
        : "=r"(r[0]), "=r"(r[1]), "=r"(r[2]), "=r"(r[3]) : "r"(a));
}
__device__ __forceinline__ void ldm_x2t(uint32_t* r, const void* p) {
    uint32_t a = (uint32_t)__cvta_generic_to_shared(p);
    asm volatile("ldmatrix.sync.aligned.m8n8.x2.trans.shared.b16 {%0,%1}, [%2];"
        : "=r"(r[0]), "=r"(r[1]) : "r"(a));
}
__device__ __forceinline__ void mma16816(float* c, const uint32_t* a, const uint32_t* b) {
    asm volatile("mma.sync.aligned.m16n8k16.row.col.f32.f16.f16.f32 "
        "{%0,%1,%2,%3}, {%4,%5,%6,%7}, {%8,%9}, {%0,%1,%2,%3};"
        : "+f"(c[0]), "+f"(c[1]), "+f"(c[2]), "+f"(c[3])
        : "r"(a[0]), "r"(a[1]), "r"(a[2]), "r"(a[3]), "r"(b[0]), "r"(b[1]));
}

__device__ __forceinline__ void split1(float v, f16& h, f16& l) {
    h = __float2half(v);
    l = __float2half(v - __half2float(h));
}

// ---------------- small prep kernels ----------------
__global__ void sq_kernel(const float* __restrict__ cond, float* __restrict__ sq) {
    const int row  = blockIdx.x * 8 + (threadIdx.x >> 5);
    const int lane = threadIdx.x & 31;
    const float4 t = reinterpret_cast<const float4*>(cond)[row * 32 + lane];
    float s = t.x * t.x + t.y * t.y + t.z * t.z + t.w * t.w;
    #pragma unroll
    for (int o = 16; o > 0; o >>= 1) s += __shfl_down_sync(0xffffffffu, s, o);
    if (lane == 0) sq[row] = s;
}

// vectorized split: 4 floats -> 4 hi + 4 lo halves per thread
__global__ void split4_kernel(const float* __restrict__ src, f16* __restrict__ hi,
                              f16* __restrict__ lo, int n4) {
    const int i = blockIdx.x * blockDim.x + threadIdx.x;
    if (i >= n4) return;
    const float4 v = reinterpret_cast<const float4*>(src)[i];
    f16 h0, l0, h1, l1, h2, l2, h3, l3;
    split1(v.x, h0, l0); split1(v.y, h1, l1);
    split1(v.z, h2, l2); split1(v.w, h3, l3);
    __half2 hh[2] = { __halves2half2(h0, h1), __halves2half2(h2, h3) };
    __half2 ll[2] = { __halves2half2(l0, l1), __halves2half2(l2, l3) };
    reinterpret_cast<uint2*>(hi)[i] = *reinterpret_cast<uint2*>(hh);
    reinterpret_cast<uint2*>(lo)[i] = *reinterpret_cast<uint2*>(ll);
}

// condT[k][n] = cond[n][k], split
__global__ void tsplit_kernel(const float* __restrict__ cond, f16* __restrict__ hi,
                              f16* __restrict__ lo) {
    const int i = blockIdx.x * blockDim.x + threadIdx.x;
    if (i >= DF * NN) return;
    const int k = i / NN, n = i % NN;
    f16 h, l; split1(cond[n * DF + k], h, l);
    hi[i] = h; lo[i] = l;
}

// x0 = concat(cond, tens), split
__global__ void concat_split_kernel(const float* __restrict__ cond, const float* __restrict__ tens,
                                    f16* __restrict__ hi, f16* __restrict__ lo) {
    const int i = blockIdx.x * blockDim.x + threadIdx.x;
    if (i >= NN * XDIM) return;
    const int r = i / XDIM, c = i % XDIM;
    const float v = (c < DF) ? cond[r * DF + c] : tens[r * DR + (c - DF)];
    f16 h, l; split1(v, h, l);
    hi[i] = h; lo[i] = l;
}

// ---------------- split-fp16 tensor-core GEMM ----------------
// C[M,N] ~= (Ah+Al)@(Bh+Bl)  (drop lo*lo).  BM=128, BK=16, warp tile 64x32.
// EPI 0: y = softplus(acc + bias[c]) -> write split fp16 (Oh, Ol)
// EPI 1: Cf = extra - (acc + bias[c])
// EPI 2: Cf = max(bias[r] + bias[c] - 2*acc, 0)      (gram keys; bias = sq)
template<int BN, int EPI>
__global__ void __launch_bounds__((BN / 32) * 64)
mma_gemm(const f16* __restrict__ Ah, const f16* __restrict__ Al,
         const f16* __restrict__ Bh, const f16* __restrict__ Bl,
         const float* __restrict__ bias, const float* __restrict__ extra,
         float* __restrict__ Cf, f16* __restrict__ Oh, f16* __restrict__ Ol,
         int M, int N, int K)
{
    constexpr int WN = BN / 32;
    constexpr int THREADS = 2 * WN * 32;
    constexpr int AST = 24;       // As row stride: 48B, conflict-free ldmatrix
    constexpr int BST = BN + 8;   // Bs row stride

    __shared__ __align__(16) f16 As[2][2][128 * AST];
    __shared__ __align__(16) f16 Bs[2][2][16 * BST];

    const int tid  = threadIdx.x;
    const int lane = tid & 31;
    const int w    = tid >> 5;
    const int wm   = w / WN;
    const int wn   = w % WN;
    const int row0 = blockIdx.y * 128;
    const int col0 = blockIdx.x * BN;

    float acc[4][4][4];
    #pragma unroll
    for (int a = 0; a < 4; a++)
        #pragma unroll
        for (int b = 0; b < 4; b++)
            #pragma unroll
            for (int c = 0; c < 4; c++) acc[a][b][c] = 0.0f;

    const int nchunk = K / 16;

    auto load_chunk = [&](int ci, int buf) {
        const int kt = ci * 16;
        #pragma unroll
        for (int s = 0; s < 2; s++) {
            const f16* Ag = s ? Al : Ah;
            for (int f = tid; f < 128 * 2; f += THREADS) {
                const int m = f >> 1, c = (f & 1) * 8;
                cpa16(&As[buf][s][m * AST + c], Ag + (size_t)(row0 + m) * K + kt + c);
            }
            const f16* Bg = s ? Bl : Bh;
            for (int f = tid; f < 16 * (BN / 8); f += THREADS) {
                const int k = f / (BN / 8), c = (f % (BN / 8)) * 8;
                cpa16(&Bs[buf][s][k * BST + c], Bg + (size_t)(kt + k) * N + col0 + c);
            }
        }
    };

    load_chunk(0, 0);
    CP_COMMIT();

    for (int ci = 0; ci < nchunk; ci++) {
        const int buf = ci & 1;
        if (ci + 1 < nchunk) load_chunk(ci + 1, buf ^ 1);
        CP_COMMIT();
        CP_WAIT1();
        __syncthreads();

        uint32_t a[4][4], b[4][2];
        const int arow = wm * 64 + (lane & 15);
        const int acol = (lane >> 4) << 3;
        const int brow = (lane & 15) * BST;
        const int bcol = wn * 32;

        // pass 1: Ahi x Blo
        #pragma unroll
        for (int mt = 0; mt < 4; mt++)
            ldm_x4(a[mt], &As[buf][0][(arow + mt * 16) * AST + acol]);
        #pragma unroll
        for (int nt = 0; nt < 4; nt++)
            ldm_x2t(b[nt], &Bs[buf][1][brow + bcol + nt * 8]);
        #pragma unroll
        for (int mt = 0; mt < 4; mt++)
            #pragma unroll
            for (int nt = 0; nt < 4; nt++) mma16816(acc[mt][nt], a[mt], b[nt]);

        // pass 2: Ahi x Bhi
        #pragma unroll
        for (int nt = 0; nt < 4; nt++)
            ldm_x2t(b[nt], &Bs[buf][0][brow + bcol + nt * 8]);
        #pragma unroll
        for (int mt = 0; mt < 4; mt++)
            #pragma unroll
            for (int nt = 0; nt < 4; nt++) mma16816(acc[mt][nt], a[mt], b[nt]);

        // pass 3: Alo x Bhi (b regs reused)
        #pragma unroll
        for (int mt = 0; mt < 4; mt++)
            ldm_x4(a[mt], &As[buf][1][(arow + mt * 16) * AST + acol]);
        #pragma unroll
        for (int mt = 0; mt < 4; mt++)
            #pragma unroll
            for (int nt = 0; nt < 4; nt++) mma16816(acc[mt][nt], a[mt], b[nt]);

        __syncthreads();
    }

    // epilogue
    #pragma unroll
    for (int mt = 0; mt < 4; mt++) {
        #pragma unroll
        for (int nt = 0; nt < 4; nt++) {
            const int r = row0 + wm * 64 + mt * 16 + (lane >> 2);
            const int c = col0 + wn * 32 + nt * 8 + ((lane & 3) << 1);
            const float* ac = acc[mt][nt];
            if constexpr (EPI == 0) {
                const float bc0 = bias[c], bc1 = bias[c + 1];
                #pragma unroll
                for (int h = 0; h < 2; h++) {
                    const int rr = r + 8 * h;
                    const float y0 = sp(ac[2 * h] + bc0);
                    const float y1 = sp(ac[2 * h + 1] + bc1);
                    f16 h0, l0, h1, l1;
                    split1(y0, h0, l0); split1(y1, h1, l1);
                    *(__half2*)(Oh + (size_t)rr * N + c) = __halves2half2(h0, h1);
                    *(__half2*)(Ol + (size_t)rr * N + c) = __halves2half2(l0, l1);
                }
            } else if constexpr (EPI == 1) {
                const float bc0 = bias[c], bc1 = bias[c + 1];
                #pragma unroll
                for (int h = 0; h < 2; h++) {
                    const size_t o = (size_t)(r + 8 * h) * N + c;
                    Cf[o]     = extra[o]     - (ac[2 * h]     + bc0);
                    Cf[o + 1] = extra[o + 1] - (ac[2 * h + 1] + bc1);
                }
            } else {
                const float sc0 = bias[c], sc1 = bias[c + 1];
                #pragma unroll
                for (int h = 0; h < 2; h++) {
                    const float sr = bias[r + 8 * h];
                    const size_t o = (size_t)(r + 8 * h) * NN + c;
                    Cf[o]     = fmaxf(sr + sc0 - 2.0f * ac[2 * h],     0.0f);
                    Cf[o + 1] = fmaxf(sr + sc1 - 2.0f * ac[2 * h + 1], 0.0f);
                }
            }
        }
    }
}

// ---------------- top-NCAND smallest per row (approx keys), register lists ------
template<int L>
__device__ __forceinline__ void insL(float x, int j, float (&v)[L], int (&id)[L]) {
    if (x >= v[L - 1]) return;
    #pragma unroll
    for (int t = L - 1; t > 0; t--) {
        const bool shf = (x < v[t - 1]);
        const bool put = !shf && (x < v[t]);
        v[t]  = shf ? v[t - 1]  : (put ? x : v[t]);
        id[t] = shf ? id[t - 1] : (put ? j : id[t]);
    }
    if (x < v[0]) { v[0] = x; id[0] = j; }
}

__global__ void topk_kernel(const float* __restrict__ key, int* __restrict__ out_cand) {
    const int row  = blockIdx.x * 8 + (threadIdx.x >> 5);
    const int lane = threadIdx.x & 31;
    const float4* k4 = reinterpret_cast<const float4*>(key + (size_t)row * NN);

    float v[NCAND]; int id[NCAND];
    #pragma unroll
    for (int t = 0; t < NCAND; t++) { v[t] = 3.0e38f; id[t] = 0x7fffffff; }

    #pragma unroll 4
    for (int j = lane; j < NN / 4; j += 32) {
        const float4 t = k4[j];
        const int b = 4 * j;
        insL<NCAND>(t.x, b,     v, id);
        insL<NCAND>(t.y, b + 1, v, id);
        insL<NCAND>(t.z, b + 2, v, id);
        insL<NCAND>(t.w, b + 3, v, id);
    }

    #pragma unroll
    for (int k = 0; k < NCAND; k++) {
        float mv = v[0]; int mi = id[0];
        #pragma unroll
        for (int off = 16; off > 0; off >>= 1) {
            const float ov = __shfl_down_sync(0xffffffffu, mv, off);
            const int   oi = __shfl_down_sync(0xffffffffu, mi, off);
            if (ov < mv || (ov == mv && oi < mi)) { mv = ov; mi = oi; }
        }
        mv = __shfl_sync(0xffffffffu, mv, 0);
        mi = __shfl_sync(0xffffffffu, mi, 0);
        if (id[0] == mi) {
            #pragma unroll
            for (int t = 0; t < NCAND - 1; t++) { v[t] = v[t + 1]; id[t] = id[t + 1]; }
            v[NCAND - 1] = 3.0e38f; id[NCAND - 1] = 0x7fffffff;
        }
        if (lane == 0) out_cand[row * NCAND + k] = mi;
    }
}

// ---------------- exact fp32 rescore of the 16 candidates -> final top-10 --------
__global__ void rescore_kernel(const float* __restrict__ cond, const float* __restrict__ sq,
                               const int* __restrict__ cand, int* __restrict__ out_idx) {
    const int row  = blockIdx.x * 8 + (threadIdx.x >> 5);
    const int lane = threadIdx.x & 31;
    const float4 cr = reinterpret_cast<const float4*>(cond)[row * 32 + lane];
    const float sr = sq[row];

    float mv = 3.0e38f; int mid = 0x7fffffff;
    #pragma unroll
    for (int c = 0; c < NCAND; c++) {
        const int j = cand[row * NCAND + c];
        const float4 cc = reinterpret_cast<const float4*>(cond)[j * 32 + lane];
        float d = cr.x * cc.x + cr.y * cc.y + cr.z * cc.z + cr.w * cc.w;
        #pragma unroll
        for (int o = 16; o > 0; o >>= 1) d += __shfl_down_sync(0xffffffffu, d, o);
        d = __shfl_sync(0xffffffffu, d, 0);
        const float k = fmaxf(sr + sq[j] - 2.0f * d, 0.0f);
        if (lane == c) { mv = k; mid = j; }
    }

    #pragma unroll
    for (int k = 0; k < TOPK; k++) {
        float bv = mv; int bi = mid;
        #pragma unroll
        for (int off = 16; off > 0; off >>= 1) {
            const float ov = __shfl_down_sync(0xffffffffu, bv, off);
            const int   oi = __shfl_down_sync(0xffffffffu, bi, off);
            if (ov < bv || (ov == bv && oi < bi)) { bv = ov; bi = oi; }
        }
        bv = __shfl_sync(0xffffffffu, bv, 0);
        bi = __shfl_sync(0xffffffffu, bi, 0);
        if (mid == bi) { mv = 3.0e38f; mid = 0x7fffffff; }
        if (lane == 0) out_idx[row * TOPK + k] = bi;
    }
}

// ---------------- final gather ----------------
__global__ void gather_kernel(const int* __restrict__ nidx, const float* __restrict__ pushed,
                              float* __restrict__ out) {
    const int t = blockIdx.x * blockDim.x + threadIdx.x;
    if (t >= NN * TOPK * 16) return;
    const int r = t >> 4, c = t & 15;
    const int j = nidx[r];
    reinterpret_cast<float4*>(out)[t] = reinterpret_cast<const float4*>(pushed)[j * 16 + c];
}

// ---------------- launch ----------------
extern "C" void kernel_launch(void* const* d_in, const int* in_sizes, int n_in,
                              void* d_out, int out_size)
{
    const float* cond = (const float*)d_in[0];
    const float* tens = (const float*)d_in[1];
    const float* Win  = (const float*)d_in[2];
    const float* b_in = (const float*)d_in[3];
    const float* W1   = (const float*)d_in[4];
    const float* b1   = (const float*)d_in[5];
    const float* W2   = (const float*)d_in[6];
    const float* b2   = (const float*)d_in[7];
    const float* W3   = (const float*)d_in[8];
    const float* b3   = (const float*)d_in[9];
    const float* Wout = (const float*)d_in[10];
    const float* bout = (const float*)d_in[11];
    float* out = (float*)d_out;

    float *key, *sq, *pushed; int *cand, *nidx;
    f16 *x0h, *x0l, *hAh, *hAl, *hBh, *hBl, *ch, *cl, *cth, *ctl;
    f16 *Wih, *Wil, *W1h, *W1l, *W2h, *W2l, *W3h, *W3l, *Woh, *Wol;
    cudaGetSymbolAddress((void**)&key, g_key);
    cudaGetSymbolAddress((void**)&sq, g_sq);
    cudaGetSymbolAddress((void**)&cand, g_cand);
    cudaGetSymbolAddress((void**)&nidx, g_nidx);
    cudaGetSymbolAddress((void**)&pushed, g_pushed);
    cudaGetSymbolAddress((void**)&x0h, g_x0h); cudaGetSymbolAddress((void**)&x0l, g_x0l);
    cudaGetSymbolAddress((void**)&hAh, g_hAh); cudaGetSymbolAddress((void**)&hAl, g_hAl);
    cudaGetSymbolAddress((void**)&hBh, g_hBh); cudaGetSymbolAddress((void**)&hBl, g_hBl);
    cudaGetSymbolAddress((void**)&ch,  g_ch);  cudaGetSymbolAddress((void**)&cl,  g_cl);
    cudaGetSymbolAddress((void**)&cth, g_cth); cudaGetSymbolAddress((void**)&ctl, g_ctl);
    cudaGetSymbolAddress((void**)&Wih, g_Wih); cudaGetSymbolAddress((void**)&Wil, g_Wil);
    cudaGetSymbolAddress((void**)&W1h, g_W1h); cudaGetSymbolAddress((void**)&W1l, g_W1l);
    cudaGetSymbolAddress((void**)&W2h, g_W2h); cudaGetSymbolAddress((void**)&W2l, g_W2l);
    cudaGetSymbolAddress((void**)&W3h, g_W3h); cudaGetSymbolAddress((void**)&W3l, g_W3l);
    cudaGetSymbolAddress((void**)&Woh, g_Woh); cudaGetSymbolAddress((void**)&Wol, g_Wol);

    // prep: norms, splits, transposes
    sq_kernel<<<NN / 8, 256>>>(cond, sq);
    split4_kernel<<<(NN * DF / 4 + 255) / 256, 256>>>(cond, ch, cl, NN * DF / 4);
    tsplit_kernel<<<(DF * NN + 255) / 256, 256>>>(cond, cth, ctl);
    concat_split_kernel<<<(NN * XDIM + 255) / 256, 256>>>(cond, tens, x0h, x0l);
    split4_kernel<<<(XDIM * HID / 4 + 255) / 256, 256>>>(Win, Wih, Wil, XDIM * HID / 4);
    split4_kernel<<<(HID * HID / 4 + 255) / 256, 256>>>(W1, W1h, W1l, HID * HID / 4);
    split4_kernel<<<(HID * HID / 4 + 255) / 256, 256>>>(W2, W2h, W2l, HID * HID / 4);
    split4_kernel<<<(HID * HID / 4 + 255) / 256, 256>>>(W3, W3h, W3l, HID * HID / 4);
    split4_kernel<<<(HID * DR / 4 + 255) / 256, 256>>>(Wout, Woh, Wol, HID * DR / 4);

    // gram -> approx clamped d2 keys (split-fp16 tensor cores)
    mma_gemm<128, 2><<<dim3(NN / 128, NN / 128), 256>>>(
        ch, cl, cth, ctl, sq, nullptr, key, nullptr, nullptr, NN, NN, DF);

    // top-16 candidates, then exact fp32 rescore -> top-10
    topk_kernel<<<NN / 8, 256>>>(key, cand);
    rescore_kernel<<<NN / 8, 256>>>(cond, sq, cand, nidx);

    // MLP over 4096 unique rows (split-fp16 tensor cores)
    mma_gemm<128, 0><<<dim3(HID / 128, NN / 128), 256>>>(
        x0h, x0l, Wih, Wil, b_in, nullptr, nullptr, hAh, hAl, NN, HID, XDIM);
    mma_gemm<128, 0><<<dim3(HID / 128, NN / 128), 256>>>(
        hAh, hAl, W1h, W1l, b1, nullptr, nullptr, hBh, hBl, NN, HID, HID);
    mma_gemm<128, 0><<<dim3(HID / 128, NN / 128), 256>>>(
        hBh, hBl, W2h, W2l, b2, nullptr, nullptr, hAh, hAl, NN, HID, HID);
    mma_gemm<128, 0><<<dim3(HID / 128, NN / 128), 256>>>(
        hAh, hAl, W3h, W3l, b3, nullptr, nullptr, hBh, hBl, NN, HID, HID);

    // output layer fused with pushforward
    mma_gemm<64, 1><<<dim3(DR / 64, NN / 128), 128>>>(
        hBh, hBl, Woh, Wol, bout, tens, pushed, nullptr, nullptr, NN, DR, HID);

    // gather
    gather_kernel<<<(NN * TOPK * 16 + 255) / 256, 256>>>(nidx, pushed, out);
}

// round 8
// speedup vs baseline: 2.6650x; 1.0483x over previous
#include <cuda_runtime.h>
#include <cuda_fp16.h>
#include <cstdint>

#define NN    4096
#define DF    128
#define DR    64
#define HID   1024
#define TOPK  10
#define NCAND 16
#define XDIM  192

typedef __half f16;

// ---------------- static scratch ----------------
__device__ float g_key[(size_t)NN * NN];
__device__ float g_sq [NN];
__device__ int   g_cand[NN * NCAND];
__device__ int   g_nidx[NN * TOPK];
__device__ float g_pushed[NN * DR];

__device__ f16 g_x0h[NN * XDIM], g_x0l[NN * XDIM];
__device__ f16 g_hAh[NN * HID],  g_hAl[NN * HID];
__device__ f16 g_hBh[NN * HID],  g_hBl[NN * HID];
__device__ f16 g_ch [NN * DF],   g_cl [NN * DF];
__device__ f16 g_cth[DF * NN],   g_ctl[DF * NN];
__device__ f16 g_Wih[XDIM * HID], g_Wil[XDIM * HID];
__device__ f16 g_W1h[HID * HID],  g_W1l[HID * HID];
__device__ f16 g_W2h[HID * HID],  g_W2l[HID * HID];
__device__ f16 g_W3h[HID * HID],  g_W3l[HID * HID];
__device__ f16 g_Woh[HID * DR],   g_Wol[HID * DR];

// ---------------- helpers ----------------
__device__ __forceinline__ float sp(float x) {
    return fmaxf(x, 0.0f) + log1pf(expf(-fabsf(x)));
}

__device__ __forceinline__ void cpa16(void* s, const void* g) {
    uint32_t sa = (uint32_t)__cvta_generic_to_shared(s);
    asm volatile("cp.async.cg.shared.global [%0], [%1], 16;" :: "r"(sa), "l"(g) : "memory");
}
#define CP_COMMIT() asm volatile("cp.async.commit_group;" ::: "memory")
#define CP_WAIT1()  asm volatile("cp.async.wait_group 1;" ::: "memory")

__device__ __forceinline__ void ldm_x4(uint32_t* r, const void* p) {
    uint32_t a = (uint32_t)__cvta_generic_to_shared(p);
    asm volatile("ldmatrix.sync.aligned.m8n8.x4.shared.b16 {%0,%1,%2,%3}, [%4];"
        : "=r"(r[0]), "=r"(r[1]), "=r"(r[2]), "=r"(r[3]) : "r"(a));
}
__device__ __forceinline__ void ldm_x2t(uint32_t* r, const void* p) {
    uint32_t a = (uint32_t)__cvta_generic_to_shared(p);
    asm volatile("ldmatrix.sync.aligned.m8n8.x2.trans.shared.b16 {%0,%1}, [%2];"
        : "=r"(r[0]), "=r"(r[1]) : "r"(a));
}
__device__ __forceinline__ void mma16816(float* c, const uint32_t* a, const uint32_t* b) {
    asm volatile("mma.sync.aligned.m16n8k16.row.col.f32.f16.f16.f32 "
        "{%0,%1,%2,%3}, {%4,%5,%6,%7}, {%8,%9}, {%0,%1,%2,%3};"
        : "+f"(c[0]), "+f"(c[1]), "+f"(c[2]), "+f"(c[3])
        : "r"(a[0]), "r"(a[1]), "r"(a[2]), "r"(a[3]), "r"(b[0]), "r"(b[1]));
}

__device__ __forceinline__ void split1(float v, f16& h, f16& l) {
    h = __float2half(v);
    l = __float2half(v - __half2float(h));
}

// ---------------- small prep kernels ----------------
__global__ void sq_kernel(const float* __restrict__ cond, float* __restrict__ sq) {
    const int row  = blockIdx.x * 8 + (threadIdx.x >> 5);
    const int lane = threadIdx.x & 31;
    const float4 t = reinterpret_cast<const float4*>(cond)[row * 32 + lane];
    float s = t.x * t.x + t.y * t.y + t.z * t.z + t.w * t.w;
    #pragma unroll
    for (int o = 16; o > 0; o >>= 1) s += __shfl_down_sync(0xffffffffu, s, o);
    if (lane == 0) sq[row] = s;
}

// vectorized split with 4x ILP per thread
__global__ void split4_kernel(const float* __restrict__ src, f16* __restrict__ hi,
                              f16* __restrict__ lo, int n4) {
    const int i0 = blockIdx.x * (blockDim.x * 4) + threadIdx.x;
    #pragma unroll
    for (int u = 0; u < 4; u++) {
        const int i = i0 + u * blockDim.x;
        if (i >= n4) return;
        const float4 v = reinterpret_cast<const float4*>(src)[i];
        f16 h0, l0, h1, l1, h2, l2, h3, l3;
        split1(v.x, h0, l0); split1(v.y, h1, l1);
        split1(v.z, h2, l2); split1(v.w, h3, l3);
        __half2 hh[2] = { __halves2half2(h0, h1), __halves2half2(h2, h3) };
        __half2 ll[2] = { __halves2half2(l0, l1), __halves2half2(l2, l3) };
        reinterpret_cast<uint2*>(hi)[i] = *reinterpret_cast<uint2*>(hh);
        reinterpret_cast<uint2*>(lo)[i] = *reinterpret_cast<uint2*>(ll);
    }
}

// condT[k][n] = cond[n][k], split
__global__ void tsplit_kernel(const float* __restrict__ cond, f16* __restrict__ hi,
                              f16* __restrict__ lo) {
    const int i = blockIdx.x * blockDim.x + threadIdx.x;
    if (i >= DF * NN) return;
    const int k = i / NN, n = i % NN;
    f16 h, l; split1(cond[n * DF + k], h, l);
    hi[i] = h; lo[i] = l;
}

// x0 = concat(cond, tens), split
__global__ void concat_split_kernel(const float* __restrict__ cond, const float* __restrict__ tens,
                                    f16* __restrict__ hi, f16* __restrict__ lo) {
    const int i = blockIdx.x * blockDim.x + threadIdx.x;
    if (i >= NN * XDIM) return;
    const int r = i / XDIM, c = i % XDIM;
    const float v = (c < DF) ? cond[r * DF + c] : tens[r * DR + (c - DF)];
    f16 h, l; split1(v, h, l);
    hi[i] = h; lo[i] = l;
}

// ---------------- split-fp16 tensor-core GEMM ----------------
// C[M,N] ~= (Ah+Al)@(Bh+Bl)  (drop lo*lo).  BM=128, BK=16, warp tile 64x32.
// EPI 0: y = softplus(acc + bias[c]) -> write split fp16 (Oh, Ol)
// EPI 1: Cf = extra - (acc + bias[c])
// EPI 2: Cf = max(bias[r] + bias[c] - 2*acc, 0)      (gram keys; bias = sq)
template<int BN, int EPI>
__global__ void __launch_bounds__((BN / 32) * 64)
mma_gemm(const f16* __restrict__ Ah, const f16* __restrict__ Al,
         const f16* __restrict__ Bh, const f16* __restrict__ Bl,
         const float* __restrict__ bias, const float* __restrict__ extra,
         float* __restrict__ Cf, f16* __restrict__ Oh, f16* __restrict__ Ol,
         int M, int N, int K)
{
    constexpr int WN = BN / 32;
    constexpr int THREADS = 2 * WN * 32;
    constexpr int AST = 24;       // As row stride: 48B, conflict-free ldmatrix
    constexpr int BST = BN + 8;   // Bs row stride

    __shared__ __align__(16) f16 As[2][2][128 * AST];
    __shared__ __align__(16) f16 Bs[2][2][16 * BST];

    const int tid  = threadIdx.x;
    const int lane = tid & 31;
    const int w    = tid >> 5;
    const int wm   = w / WN;
    const int wn   = w % WN;
    const int row0 = blockIdx.y * 128;
    const int col0 = blockIdx.x * BN;

    float acc[4][4][4];
    #pragma unroll
    for (int a = 0; a < 4; a++)
        #pragma unroll
        for (int b = 0; b < 4; b++)
            #pragma unroll
            for (int c = 0; c < 4; c++) acc[a][b][c] = 0.0f;

    const int nchunk = K / 16;

    auto load_chunk = [&](int ci, int buf) {
        const int kt = ci * 16;
        #pragma unroll
        for (int s = 0; s < 2; s++) {
            const f16* Ag = s ? Al : Ah;
            for (int f = tid; f < 128 * 2; f += THREADS) {
                const int m = f >> 1, c = (f & 1) * 8;
                cpa16(&As[buf][s][m * AST + c], Ag + (size_t)(row0 + m) * K + kt + c);
            }
            const f16* Bg = s ? Bl : Bh;
            for (int f = tid; f < 16 * (BN / 8); f += THREADS) {
                const int k = f / (BN / 8), c = (f % (BN / 8)) * 8;
                cpa16(&Bs[buf][s][k * BST + c], Bg + (size_t)(kt + k) * N + col0 + c);
            }
        }
    };

    load_chunk(0, 0);
    CP_COMMIT();

    for (int ci = 0; ci < nchunk; ci++) {
        const int buf = ci & 1;
        if (ci + 1 < nchunk) load_chunk(ci + 1, buf ^ 1);
        CP_COMMIT();
        CP_WAIT1();
        __syncthreads();

        uint32_t a[4][4], b[4][2];
        const int arow = wm * 64 + (lane & 15);
        const int acol = (lane >> 4) << 3;
        const int brow = (lane & 15) * BST;
        const int bcol = wn * 32;

        // pass 1: Ahi x Blo
        #pragma unroll
        for (int mt = 0; mt < 4; mt++)
            ldm_x4(a[mt], &As[buf][0][(arow + mt * 16) * AST + acol]);
        #pragma unroll
        for (int nt = 0; nt < 4; nt++)
            ldm_x2t(b[nt], &Bs[buf][1][brow + bcol + nt * 8]);
        #pragma unroll
        for (int mt = 0; mt < 4; mt++)
            #pragma unroll
            for (int nt = 0; nt < 4; nt++) mma16816(acc[mt][nt], a[mt], b[nt]);

        // pass 2: Ahi x Bhi
        #pragma unroll
        for (int nt = 0; nt < 4; nt++)
            ldm_x2t(b[nt], &Bs[buf][0][brow + bcol + nt * 8]);
        #pragma unroll
        for (int mt = 0; mt < 4; mt++)
            #pragma unroll
            for (int nt = 0; nt < 4; nt++) mma16816(acc[mt][nt], a[mt], b[nt]);

        // pass 3: Alo x Bhi (b regs reused)
        #pragma unroll
        for (int mt = 0; mt < 4; mt++)
            ldm_x4(a[mt], &As[buf][1][(arow + mt * 16) * AST + acol]);
        #pragma unroll
        for (int mt = 0; mt < 4; mt++)
            #pragma unroll
            for (int nt = 0; nt < 4; nt++) mma16816(acc[mt][nt], a[mt], b[nt]);

        __syncthreads();
    }

    // epilogue
    #pragma unroll
    for (int mt = 0; mt < 4; mt++) {
        #pragma unroll
        for (int nt = 0; nt < 4; nt++) {
            const int r = row0 + wm * 64 + mt * 16 + (lane >> 2);
            const int c = col0 + wn * 32 + nt * 8 + ((lane & 3) << 1);
            const float* ac = acc[mt][nt];
            if constexpr (EPI == 0) {
                const float bc0 = bias[c], bc1 = bias[c + 1];
                #pragma unroll
                for (int h = 0; h < 2; h++) {
                    const int rr = r + 8 * h;
                    const float y0 = sp(ac[2 * h] + bc0);
                    const float y1 = sp(ac[2 * h + 1] + bc1);
                    f16 h0, l0, h1, l1;
                    split1(y0, h0, l0); split1(y1, h1, l1);
                    *(__half2*)(Oh + (size_t)rr * N + c) = __halves2half2(h0, h1);
                    *(__half2*)(Ol + (size_t)rr * N + c) = __halves2half2(l0, l1);
                }
            } else if constexpr (EPI == 1) {
                const float bc0 = bias[c], bc1 = bias[c + 1];
                #pragma unroll
                for (int h = 0; h < 2; h++) {
                    const size_t o = (size_t)(r + 8 * h) * N + c;
                    Cf[o]     = extra[o]     - (ac[2 * h]     + bc0);
                    Cf[o + 1] = extra[o + 1] - (ac[2 * h + 1] + bc1);
                }
            } else {
                const float sc0 = bias[c], sc1 = bias[c + 1];
                #pragma unroll
                for (int h = 0; h < 2; h++) {
                    const float sr = bias[r + 8 * h];
                    const size_t o = (size_t)(r + 8 * h) * NN + c;
                    Cf[o]     = fmaxf(sr + sc0 - 2.0f * ac[2 * h],     0.0f);
                    Cf[o + 1] = fmaxf(sr + sc1 - 2.0f * ac[2 * h + 1], 0.0f);
                }
            }
        }
    }
}

// ---------------- top-NCAND smallest per row (approx keys), register lists ------
template<int L>
__device__ __forceinline__ void insL(float x, int j, float (&v)[L], int (&id)[L]) {
    if (x >= v[L - 1]) return;
    #pragma unroll
    for (int t = L - 1; t > 0; t--) {
        const bool shf = (x < v[t - 1]);
        const bool put = !shf && (x < v[t]);
        v[t]  = shf ? v[t - 1]  : (put ? x : v[t]);
        id[t] = shf ? id[t - 1] : (put ? j : id[t]);
    }
    if (x < v[0]) { v[0] = x; id[0] = j; }
}

__global__ void topk_kernel(const float* __restrict__ key, int* __restrict__ out_cand) {
    const int row  = blockIdx.x * 8 + (threadIdx.x >> 5);
    const int lane = threadIdx.x & 31;
    const float4* k4 = reinterpret_cast<const float4*>(key + (size_t)row * NN);

    float v[NCAND]; int id[NCAND];
    #pragma unroll
    for (int t = 0; t < NCAND; t++) { v[t] = 3.0e38f; id[t] = 0x7fffffff; }

    #pragma unroll 4
    for (int j = lane; j < NN / 4; j += 32) {
        const float4 t = k4[j];
        const int b = 4 * j;
        insL<NCAND>(t.x, b,     v, id);
        insL<NCAND>(t.y, b + 1, v, id);
        insL<NCAND>(t.z, b + 2, v, id);
        insL<NCAND>(t.w, b + 3, v, id);
    }

    #pragma unroll
    for (int k = 0; k < NCAND; k++) {
        float mv = v[0]; int mi = id[0];
        #pragma unroll
        for (int off = 16; off > 0; off >>= 1) {
            const float ov = __shfl_down_sync(0xffffffffu, mv, off);
            const int   oi = __shfl_down_sync(0xffffffffu, mi, off);
            if (ov < mv || (ov == mv && oi < mi)) { mv = ov; mi = oi; }
        }
        mv = __shfl_sync(0xffffffffu, mv, 0);
        mi = __shfl_sync(0xffffffffu, mi, 0);
        if (id[0] == mi) {
            #pragma unroll
            for (int t = 0; t < NCAND - 1; t++) { v[t] = v[t + 1]; id[t] = id[t + 1]; }
            v[NCAND - 1] = 3.0e38f; id[NCAND - 1] = 0x7fffffff;
        }
        if (lane == 0) out_cand[row * NCAND + k] = mi;
    }
}

// ---------------- exact fp32 rescore of the 16 candidates -> final top-10 --------
__global__ void rescore_kernel(const float* __restrict__ cond, const float* __restrict__ sq,
                               const int* __restrict__ cand, int* __restrict__ out_idx) {
    const int row  = blockIdx.x * 8 + (threadIdx.x >> 5);
    const int lane = threadIdx.x & 31;
    const float4 cr = reinterpret_cast<const float4*>(cond)[row * 32 + lane];
    const float sr = sq[row];

    float mv = 3.0e38f; int mid = 0x7fffffff;
    #pragma unroll
    for (int c = 0; c < NCAND; c++) {
        const int j = cand[row * NCAND + c];
        const float4 cc = reinterpret_cast<const float4*>(cond)[j * 32 + lane];
        float d = cr.x * cc.x + cr.y * cc.y + cr.z * cc.z + cr.w * cc.w;
        #pragma unroll
        for (int o = 16; o > 0; o >>= 1) d += __shfl_down_sync(0xffffffffu, d, o);
        d = __shfl_sync(0xffffffffu, d, 0);
        const float k = fmaxf(sr + sq[j] - 2.0f * d, 0.0f);
        if (lane == c) { mv = k; mid = j; }
    }

    #pragma unroll
    for (int k = 0; k < TOPK; k++) {
        float bv = mv; int bi = mid;
        #pragma unroll
        for (int off = 16; off > 0; off >>= 1) {
            const float ov = __shfl_down_sync(0xffffffffu, bv, off);
            const int   oi = __shfl_down_sync(0xffffffffu, bi, off);
            if (ov < bv || (ov == bv && oi < bi)) { bv = ov; bi = oi; }
        }
        bv = __shfl_sync(0xffffffffu, bv, 0);
        bi = __shfl_sync(0xffffffffu, bi, 0);
        if (mid == bi) { mv = 3.0e38f; mid = 0x7fffffff; }
        if (lane == 0) out_idx[row * TOPK + k] = bi;
    }
}

// ---------------- final gather ----------------
__global__ void gather_kernel(const int* __restrict__ nidx, const float* __restrict__ pushed,
                              float* __restrict__ out) {
    const int t = blockIdx.x * blockDim.x + threadIdx.x;
    if (t >= NN * TOPK * 16) return;
    const int r = t >> 4, c = t & 15;
    const int j = nidx[r];
    reinterpret_cast<float4*>(out)[t] = reinterpret_cast<const float4*>(pushed)[j * 16 + c];
}

// ---------------- launch ----------------
extern "C" void kernel_launch(void* const* d_in, const int* in_sizes, int n_in,
                              void* d_out, int out_size)
{
    const float* cond = (const float*)d_in[0];
    const float* tens = (const float*)d_in[1];
    const float* Win  = (const float*)d_in[2];
    const float* b_in = (const float*)d_in[3];
    const float* W1   = (const float*)d_in[4];
    const float* b1   = (const float*)d_in[5];
    const float* W2   = (const float*)d_in[6];
    const float* b2   = (const float*)d_in[7];
    const float* W3   = (const float*)d_in[8];
    const float* b3   = (const float*)d_in[9];
    const float* Wout = (const float*)d_in[10];
    const float* bout = (const float*)d_in[11];
    float* out = (float*)d_out;

    float *key, *sq, *pushed; int *cand, *nidx;
    f16 *x0h, *x0l, *hAh, *hAl, *hBh, *hBl, *ch, *cl, *cth, *ctl;
    f16 *Wih, *Wil, *W1h, *W1l, *W2h, *W2l, *W3h, *W3l, *Woh, *Wol;
    cudaGetSymbolAddress((void**)&key, g_key);
    cudaGetSymbolAddress((void**)&sq, g_sq);
    cudaGetSymbolAddress((void**)&cand, g_cand);
    cudaGetSymbolAddress((void**)&nidx, g_nidx);
    cudaGetSymbolAddress((void**)&pushed, g_pushed);
    cudaGetSymbolAddress((void**)&x0h, g_x0h); cudaGetSymbolAddress((void**)&x0l, g_x0l);
    cudaGetSymbolAddress((void**)&hAh, g_hAh); cudaGetSymbolAddress((void**)&hAl, g_hAl);
    cudaGetSymbolAddress((void**)&hBh, g_hBh); cudaGetSymbolAddress((void**)&hBl, g_hBl);
    cudaGetSymbolAddress((void**)&ch,  g_ch);  cudaGetSymbolAddress((void**)&cl,  g_cl);
    cudaGetSymbolAddress((void**)&cth, g_cth); cudaGetSymbolAddress((void**)&ctl, g_ctl);
    cudaGetSymbolAddress((void**)&Wih, g_Wih); cudaGetSymbolAddress((void**)&Wil, g_Wil);
    cudaGetSymbolAddress((void**)&W1h, g_W1h); cudaGetSymbolAddress((void**)&W1l, g_W1l);
    cudaGetSymbolAddress((void**)&W2h, g_W2h); cudaGetSymbolAddress((void**)&W2l, g_W2l);
    cudaGetSymbolAddress((void**)&W3h, g_W3h); cudaGetSymbolAddress((void**)&W3l, g_W3l);
    cudaGetSymbolAddress((void**)&Woh, g_Woh); cudaGetSymbolAddress((void**)&Wol, g_Wol);

    // lazy-create side stream + events (first call is outside graph capture)
    static cudaStream_t s2 = nullptr;
    static cudaEvent_t evF = nullptr, evJ = nullptr;
    if (s2 == nullptr) {
        cudaStreamCreateWithFlags(&s2, cudaStreamNonBlocking);
        cudaEventCreateWithFlags(&evF, cudaEventDisableTiming);
        cudaEventCreateWithFlags(&evJ, cudaEventDisableTiming);
    }

    // ---- prep needed by the gram chain (default stream) ----
    sq_kernel<<<NN / 8, 256>>>(cond, sq);
    split4_kernel<<<(NN * DF / 4 + 1023) / 1024, 256>>>(cond, ch, cl, NN * DF / 4);
    tsplit_kernel<<<(DF * NN + 255) / 256, 256>>>(cond, cth, ctl);

    // ---- fork: gram -> topk -> rescore on side stream ----
    cudaEventRecord(evF, 0);
    cudaStreamWaitEvent(s2, evF, 0);
    mma_gemm<128, 2><<<dim3(NN / 128, NN / 128), 256, 0, s2>>>(
        ch, cl, cth, ctl, sq, nullptr, key, nullptr, nullptr, NN, NN, DF);
    topk_kernel<<<NN / 8, 256, 0, s2>>>(key, cand);
    rescore_kernel<<<NN / 8, 256, 0, s2>>>(cond, sq, cand, nidx);
    cudaEventRecord(evJ, s2);

    // ---- MLP chain (default stream, overlaps with side stream) ----
    concat_split_kernel<<<(NN * XDIM + 255) / 256, 256>>>(cond, tens, x0h, x0l);
    split4_kernel<<<(XDIM * HID / 4 + 1023) / 1024, 256>>>(Win, Wih, Wil, XDIM * HID / 4);
    split4_kernel<<<(HID * HID / 4 + 1023) / 1024, 256>>>(W1, W1h, W1l, HID * HID / 4);
    split4_kernel<<<(HID * HID / 4 + 1023) / 1024, 256>>>(W2, W2h, W2l, HID * HID / 4);
    split4_kernel<<<(HID * HID / 4 + 1023) / 1024, 256>>>(W3, W3h, W3l, HID * HID / 4);
    split4_kernel<<<(HID * DR / 4 + 1023) / 1024, 256>>>(Wout, Woh, Wol, HID * DR / 4);

    mma_gemm<128, 0><<<dim3(HID / 128, NN / 128), 256>>>(
        x0h, x0l, Wih, Wil, b_in, nullptr, nullptr, hAh, hAl, NN, HID, XDIM);
    mma_gemm<128, 0><<<dim3(HID / 128, NN / 128), 256>>>(
        hAh, hAl, W1h, W1l, b1, nullptr, nullptr, hBh, hBl, NN, HID, HID);
    mma_gemm<128, 0><<<dim3(HID / 128, NN / 128), 256>>>(
        hBh, hBl, W2h, W2l, b2, nullptr, nullptr, hAh, hAl, NN, HID, HID);
    mma_gemm<128, 0><<<dim3(HID / 128, NN / 128), 256>>>(
        hAh, hAl, W3h, W3l, b3, nullptr, nullptr, hBh, hBl, NN, HID, HID);

    mma_gemm<64, 1><<<dim3(DR / 64, NN / 128), 128>>>(
        hBh, hBl, Woh, Wol, bout, tens, pushed, nullptr, nullptr, NN, DR, HID);

    // ---- join, then gather ----
    cudaStreamWaitEvent(0, evJ, 0);
    gather_kernel<<<(NN * TOPK * 16 + 255) / 256, 256>>>(nidx, pushed, out);
}

// round 9
// speedup vs baseline: 2.6836x; 1.0070x over previous
#include <cuda_runtime.h>
#include <cuda_fp16.h>
#include <cstdint>

#define NN    4096
#define DF    128
#define DR    64
#define HID   1024
#define TOPK  10
#define NCAND 16
#define XDIM  192

typedef __half f16;

// ---------------- static scratch ----------------
__device__ float g_key[(size_t)NN * NN];
__device__ float g_sq [NN];
__device__ int   g_cand[NN * NCAND];
__device__ int   g_nidx[NN * TOPK];
__device__ float g_pushed[NN * DR];

__device__ f16 g_x0h[NN * XDIM], g_x0l[NN * XDIM];
__device__ f16 g_hAh[NN * HID],  g_hAl[NN * HID];
__device__ f16 g_hBh[NN * HID],  g_hBl[NN * HID];
__device__ f16 g_ch [NN * DF],   g_cl [NN * DF];
__device__ f16 g_cth[DF * NN],   g_ctl[DF * NN];
__device__ f16 g_Wih[XDIM * HID], g_Wil[XDIM * HID];
__device__ f16 g_W1h[HID * HID],  g_W1l[HID * HID];
__device__ f16 g_W2h[HID * HID],  g_W2l[HID * HID];
__device__ f16 g_W3h[HID * HID],  g_W3l[HID * HID];
__device__ f16 g_Woh[HID * DR],   g_Wol[HID * DR];

// ---------------- helpers ----------------
__device__ __forceinline__ float sp(float x) {
    return fmaxf(x, 0.0f) + log1pf(expf(-fabsf(x)));
}

__device__ __forceinline__ void cpa16(void* s, const void* g) {
    uint32_t sa = (uint32_t)__cvta_generic_to_shared(s);
    asm volatile("cp.async.cg.shared.global [%0], [%1], 16;" :: "r"(sa), "l"(g) : "memory");
}
#define CP_COMMIT() asm volatile("cp.async.commit_group;" ::: "memory")
#define CP_WAIT1()  asm volatile("cp.async.wait_group 1;" ::: "memory")

__device__ __forceinline__ void ldm_x4(uint32_t* r, const void* p) {
    uint32_t a = (uint32_t)__cvta_generic_to_shared(p);
    asm volatile("ldmatrix.sync.aligned.m8n8.x4.shared.b16 {%0,%1,%2,%3}, [%4];"
        : "=r"(r[0]), "=r"(r[1]), "=r"(r[2]), "=r"(r[3]) : "r"(a));
}
__device__ __forceinline__ void ldm_x2t(uint32_t* r, const void* p) {
    uint32_t a = (uint32_t)__cvta_generic_to_shared(p);
    asm volatile("ldmatrix.sync.aligned.m8n8.x2.trans.shared.b16 {%0,%1}, [%2];"
        : "=r"(r[0]), "=r"(r[1]) : "r"(a));
}
__device__ __forceinline__ void mma16816(float* c, const uint32_t* a, const uint32_t* b) {
    asm volatile("mma.sync.aligned.m16n8k16.row.col.f32.f16.f16.f32 "
        "{%0,%1,%2,%3}, {%4,%5,%6,%7}, {%8,%9}, {%0,%1,%2,%3};"
        : "+f"(c[0]), "+f"(c[1]), "+f"(c[2]), "+f"(c[3])
        : "r"(a[0]), "r"(a[1]), "r"(a[2]), "r"(a[3]), "r"(b[0]), "r"(b[1]));
}

__device__ __forceinline__ void split1(float v, f16& h, f16& l) {
    h = __float2half(v);
    l = __float2half(v - __half2float(h));
}

// ---------------- small prep kernels ----------------
__global__ void sq_kernel(const float* __restrict__ cond, float* __restrict__ sq) {
    const int row  = blockIdx.x * 8 + (threadIdx.x >> 5);
    const int lane = threadIdx.x & 31;
    const float4 t = reinterpret_cast<const float4*>(cond)[row * 32 + lane];
    float s = t.x * t.x + t.y * t.y + t.z * t.z + t.w * t.w;
    #pragma unroll
    for (int o = 16; o > 0; o >>= 1) s += __shfl_down_sync(0xffffffffu, s, o);
    if (lane == 0) sq[row] = s;
}

// vectorized split with 4x ILP per thread
__global__ void split4_kernel(const float* __restrict__ src, f16* __restrict__ hi,
                              f16* __restrict__ lo, int n4) {
    const int i0 = blockIdx.x * (blockDim.x * 4) + threadIdx.x;
    #pragma unroll
    for (int u = 0; u < 4; u++) {
        const int i = i0 + u * blockDim.x;
        if (i >= n4) return;
        const float4 v = reinterpret_cast<const float4*>(src)[i];
        f16 h0, l0, h1, l1, h2, l2, h3, l3;
        split1(v.x, h0, l0); split1(v.y, h1, l1);
        split1(v.z, h2, l2); split1(v.w, h3, l3);
        __half2 hh[2] = { __halves2half2(h0, h1), __halves2half2(h2, h3) };
        __half2 ll[2] = { __halves2half2(l0, l1), __halves2half2(l2, l3) };
        reinterpret_cast<uint2*>(hi)[i] = *reinterpret_cast<uint2*>(hh);
        reinterpret_cast<uint2*>(lo)[i] = *reinterpret_cast<uint2*>(ll);
    }
}

// condT[k][n] = cond[n][k], split
__global__ void tsplit_kernel(const float* __restrict__ cond, f16* __restrict__ hi,
                              f16* __restrict__ lo) {
    const int i = blockIdx.x * blockDim.x + threadIdx.x;
    if (i >= DF * NN) return;
    const int k = i / NN, n = i % NN;
    f16 h, l; split1(cond[n * DF + k], h, l);
    hi[i] = h; lo[i] = l;
}

// x0 = concat(cond, tens), split
__global__ void concat_split_kernel(const float* __restrict__ cond, const float* __restrict__ tens,
                                    f16* __restrict__ hi, f16* __restrict__ lo) {
    const int i = blockIdx.x * blockDim.x + threadIdx.x;
    if (i >= NN * XDIM) return;
    const int r = i / XDIM, c = i % XDIM;
    const float v = (c < DF) ? cond[r * DF + c] : tens[r * DR + (c - DF)];
    f16 h, l; split1(v, h, l);
    hi[i] = h; lo[i] = l;
}

// ---------------- split-fp16 tensor-core GEMM ----------------
// C[M,N] ~= (Ah+Al)@(Bh+Bl)  (drop lo*lo).  BM=128, BK=16, warp tile 64x32.
// EPI 0: y = softplus(acc + bias[c]) -> write split fp16 (Oh, Ol)
// EPI 1: Cf = extra - (acc + bias[c])
// EPI 2: Cf = max(bias[r] + bias[c] - 2*acc, 0)      (gram keys; bias = sq)
template<int BN, int EPI>
__global__ void __launch_bounds__((BN / 32) * 64, 2)
mma_gemm(const f16* __restrict__ Ah, const f16* __restrict__ Al,
         const f16* __restrict__ Bh, const f16* __restrict__ Bl,
         const float* __restrict__ bias, const float* __restrict__ extra,
         float* __restrict__ Cf, f16* __restrict__ Oh, f16* __restrict__ Ol,
         int M, int N, int K)
{
    constexpr int WN = BN / 32;
    constexpr int THREADS = 2 * WN * 32;
    constexpr int AST = 24;       // As row stride: 48B, conflict-free ldmatrix
    constexpr int BST = BN + 8;   // Bs row stride

    __shared__ __align__(16) f16 As[2][2][128 * AST];
    __shared__ __align__(16) f16 Bs[2][2][16 * BST];

    const int tid  = threadIdx.x;
    const int lane = tid & 31;
    const int w    = tid >> 5;
    const int wm   = w / WN;
    const int wn   = w % WN;
    const int row0 = blockIdx.y * 128;
    const int col0 = blockIdx.x * BN;

    float acc[4][4][4];
    #pragma unroll
    for (int a = 0; a < 4; a++)
        #pragma unroll
        for (int b = 0; b < 4; b++)
            #pragma unroll
            for (int c = 0; c < 4; c++) acc[a][b][c] = 0.0f;

    const int nchunk = K / 16;

    auto load_chunk = [&](int ci, int buf) {
        const int kt = ci * 16;
        #pragma unroll
        for (int s = 0; s < 2; s++) {
            const f16* Ag = s ? Al : Ah;
            for (int f = tid; f < 128 * 2; f += THREADS) {
                const int m = f >> 1, c = (f & 1) * 8;
                cpa16(&As[buf][s][m * AST + c], Ag + (size_t)(row0 + m) * K + kt + c);
            }
            const f16* Bg = s ? Bl : Bh;
            for (int f = tid; f < 16 * (BN / 8); f += THREADS) {
                const int k = f / (BN / 8), c = (f % (BN / 8)) * 8;
                cpa16(&Bs[buf][s][k * BST + c], Bg + (size_t)(kt + k) * N + col0 + c);
            }
        }
    };

    load_chunk(0, 0);
    CP_COMMIT();

    for (int ci = 0; ci < nchunk; ci++) {
        const int buf = ci & 1;
        if (ci + 1 < nchunk) load_chunk(ci + 1, buf ^ 1);
        CP_COMMIT();
        CP_WAIT1();
        __syncthreads();

        uint32_t a[4][4], b[4][2];
        const int arow = wm * 64 + (lane & 15);
        const int acol = (lane >> 4) << 3;
        const int brow = (lane & 15) * BST;
        const int bcol = wn * 32;

        // pass 1: Ahi x Blo
        #pragma unroll
        for (int mt = 0; mt < 4; mt++)
            ldm_x4(a[mt], &As[buf][0][(arow + mt * 16) * AST + acol]);
        #pragma unroll
        for (int nt = 0; nt < 4; nt++)
            ldm_x2t(b[nt], &Bs[buf][1][brow + bcol + nt * 8]);
        #pragma unroll
        for (int mt = 0; mt < 4; mt++)
            #pragma unroll
            for (int nt = 0; nt < 4; nt++) mma16816(acc[mt][nt], a[mt], b[nt]);

        // pass 2: Ahi x Bhi
        #pragma unroll
        for (int nt = 0; nt < 4; nt++)
            ldm_x2t(b[nt], &Bs[buf][0][brow + bcol + nt * 8]);
        #pragma unroll
        for (int mt = 0; mt < 4; mt++)
            #pragma unroll
            for (int nt = 0; nt < 4; nt++) mma16816(acc[mt][nt], a[mt], b[nt]);

        // pass 3: Alo x Bhi (b regs reused)
        #pragma unroll
        for (int mt = 0; mt < 4; mt++)
            ldm_x4(a[mt], &As[buf][1][(arow + mt * 16) * AST + acol]);
        #pragma unroll
        for (int mt = 0; mt < 4; mt++)
            #pragma unroll
            for (int nt = 0; nt < 4; nt++) mma16816(acc[mt][nt], a[mt], b[nt]);

        __syncthreads();
    }

    // epilogue
    #pragma unroll
    for (int mt = 0; mt < 4; mt++) {
        #pragma unroll
        for (int nt = 0; nt < 4; nt++) {
            const int r = row0 + wm * 64 + mt * 16 + (lane >> 2);
            const int c = col0 + wn * 32 + nt * 8 + ((lane & 3) << 1);
            const float* ac = acc[mt][nt];
            if constexpr (EPI == 0) {
                const float bc0 = bias[c], bc1 = bias[c + 1];
                #pragma unroll
                for (int h = 0; h < 2; h++) {
                    const int rr = r + 8 * h;
                    const float y0 = sp(ac[2 * h] + bc0);
                    const float y1 = sp(ac[2 * h + 1] + bc1);
                    f16 h0, l0, h1, l1;
                    split1(y0, h0, l0); split1(y1, h1, l1);
                    *(__half2*)(Oh + (size_t)rr * N + c) = __halves2half2(h0, h1);
                    *(__half2*)(Ol + (size_t)rr * N + c) = __halves2half2(l0, l1);
                }
            } else if constexpr (EPI == 1) {
                const float bc0 = bias[c], bc1 = bias[c + 1];
                #pragma unroll
                for (int h = 0; h < 2; h++) {
                    const size_t o = (size_t)(r + 8 * h) * N + c;
                    Cf[o]     = extra[o]     - (ac[2 * h]     + bc0);
                    Cf[o + 1] = extra[o + 1] - (ac[2 * h + 1] + bc1);
                }
            } else {
                const float sc0 = bias[c], sc1 = bias[c + 1];
                #pragma unroll
                for (int h = 0; h < 2; h++) {
                    const float sr = bias[r + 8 * h];
                    const size_t o = (size_t)(r + 8 * h) * NN + c;
                    Cf[o]     = fmaxf(sr + sc0 - 2.0f * ac[2 * h],     0.0f);
                    Cf[o + 1] = fmaxf(sr + sc1 - 2.0f * ac[2 * h + 1], 0.0f);
                }
            }
        }
    }
}

// ---------------- top-NCAND smallest per row (approx keys), register lists ------
template<int L>
__device__ __forceinline__ void insL(float x, int j, float (&v)[L], int (&id)[L]) {
    if (x >= v[L - 1]) return;
    #pragma unroll
    for (int t = L - 1; t > 0; t--) {
        const bool shf = (x < v[t - 1]);
        const bool put = !shf && (x < v[t]);
        v[t]  = shf ? v[t - 1]  : (put ? x : v[t]);
        id[t] = shf ? id[t - 1] : (put ? j : id[t]);
    }
    if (x < v[0]) { v[0] = x; id[0] = j; }
}

__global__ void topk_kernel(const float* __restrict__ key, int* __restrict__ out_cand) {
    const int row  = blockIdx.x * 8 + (threadIdx.x >> 5);
    const int lane = threadIdx.x & 31;
    const float4* k4 = reinterpret_cast<const float4*>(key + (size_t)row * NN);

    float v[NCAND]; int id[NCAND];
    #pragma unroll
    for (int t = 0; t < NCAND; t++) { v[t] = 3.0e38f; id[t] = 0x7fffffff; }

    #pragma unroll 4
    for (int j = lane; j < NN / 4; j += 32) {
        const float4 t = k4[j];
        const int b = 4 * j;
        insL<NCAND>(t.x, b,     v, id);
        insL<NCAND>(t.y, b + 1, v, id);
        insL<NCAND>(t.z, b + 2, v, id);
        insL<NCAND>(t.w, b + 3, v, id);
    }

    #pragma unroll
    for (int k = 0; k < NCAND; k++) {
        float mv = v[0]; int mi = id[0];
        #pragma unroll
        for (int off = 16; off > 0; off >>= 1) {
            const float ov = __shfl_down_sync(0xffffffffu, mv, off);
            const int   oi = __shfl_down_sync(0xffffffffu, mi, off);
            if (ov < mv || (ov == mv && oi < mi)) { mv = ov; mi = oi; }
        }
        mv = __shfl_sync(0xffffffffu, mv, 0);
        mi = __shfl_sync(0xffffffffu, mi, 0);
        if (id[0] == mi) {
            #pragma unroll
            for (int t = 0; t < NCAND - 1; t++) { v[t] = v[t + 1]; id[t] = id[t + 1]; }
            v[NCAND - 1] = 3.0e38f; id[NCAND - 1] = 0x7fffffff;
        }
        if (lane == 0) out_cand[row * NCAND + k] = mi;
    }
}

// ---------------- exact fp32 rescore of the 16 candidates -> final top-10 --------
__global__ void rescore_kernel(const float* __restrict__ cond, const float* __restrict__ sq,
                               const int* __restrict__ cand, int* __restrict__ out_idx) {
    const int row  = blockIdx.x * 8 + (threadIdx.x >> 5);
    const int lane = threadIdx.x & 31;
    const float4 cr = reinterpret_cast<const float4*>(cond)[row * 32 + lane];
    const float sr = sq[row];

    float mv = 3.0e38f; int mid = 0x7fffffff;
    #pragma unroll
    for (int c = 0; c < NCAND; c++) {
        const int j = cand[row * NCAND + c];
        const float4 cc = reinterpret_cast<const float4*>(cond)[j * 32 + lane];
        float d = cr.x * cc.x + cr.y * cc.y + cr.z * cc.z + cr.w * cc.w;
        #pragma unroll
        for (int o = 16; o > 0; o >>= 1) d += __shfl_down_sync(0xffffffffu, d, o);
        d = __shfl_sync(0xffffffffu, d, 0);
        const float k = fmaxf(sr + sq[j] - 2.0f * d, 0.0f);
        if (lane == c) { mv = k; mid = j; }
    }

    #pragma unroll
    for (int k = 0; k < TOPK; k++) {
        float bv = mv; int bi = mid;
        #pragma unroll
        for (int off = 16; off > 0; off >>= 1) {
            const float ov = __shfl_down_sync(0xffffffffu, bv, off);
            const int   oi = __shfl_down_sync(0xffffffffu, bi, off);
            if (ov < bv || (ov == bv && oi < bi)) { bv = ov; bi = oi; }
        }
        bv = __shfl_sync(0xffffffffu, bv, 0);
        bi = __shfl_sync(0xffffffffu, bi, 0);
        if (mid == bi) { mv = 3.0e38f; mid = 0x7fffffff; }
        if (lane == 0) out_idx[row * TOPK + k] = bi;
    }
}

// ---------------- final gather ----------------
__global__ void gather_kernel(const int* __restrict__ nidx, const float* __restrict__ pushed,
                              float* __restrict__ out) {
    const int t = blockIdx.x * blockDim.x + threadIdx.x;
    if (t >= NN * TOPK * 16) return;
    const int r = t >> 4, c = t & 15;
    const int j = nidx[r];
    reinterpret_cast<float4*>(out)[t] = reinterpret_cast<const float4*>(pushed)[j * 16 + c];
}

// ---------------- launch ----------------
extern "C" void kernel_launch(void* const* d_in, const int* in_sizes, int n_in,
                              void* d_out, int out_size)
{
    const float* cond = (const float*)d_in[0];
    const float* tens = (const float*)d_in[1];
    const float* Win  = (const float*)d_in[2];
    const float* b_in = (const float*)d_in[3];
    const float* W1   = (const float*)d_in[4];
    const float* b1   = (const float*)d_in[5];
    const float* W2   = (const float*)d_in[6];
    const float* b2   = (const float*)d_in[7];
    const float* W3   = (const float*)d_in[8];
    const float* b3   = (const float*)d_in[9];
    const float* Wout = (const float*)d_in[10];
    const float* bout = (const float*)d_in[11];
    float* out = (float*)d_out;

    float *key, *sq, *pushed; int *cand, *nidx;
    f16 *x0h, *x0l, *hAh, *hAl, *hBh, *hBl, *ch, *cl, *cth, *ctl;
    f16 *Wih, *Wil, *W1h, *W1l, *W2h, *W2l, *W3h, *W3l, *Woh, *Wol;
    cudaGetSymbolAddress((void**)&key, g_key);
    cudaGetSymbolAddress((void**)&sq, g_sq);
    cudaGetSymbolAddress((void**)&cand, g_cand);
    cudaGetSymbolAddress((void**)&nidx, g_nidx);
    cudaGetSymbolAddress((void**)&pushed, g_pushed);
    cudaGetSymbolAddress((void**)&x0h, g_x0h); cudaGetSymbolAddress((void**)&x0l, g_x0l);
    cudaGetSymbolAddress((void**)&hAh, g_hAh); cudaGetSymbolAddress((void**)&hAl, g_hAl);
    cudaGetSymbolAddress((void**)&hBh, g_hBh); cudaGetSymbolAddress((void**)&hBl, g_hBl);
    cudaGetSymbolAddress((void**)&ch,  g_ch);  cudaGetSymbolAddress((void**)&cl,  g_cl);
    cudaGetSymbolAddress((void**)&cth, g_cth); cudaGetSymbolAddress((void**)&ctl, g_ctl);
    cudaGetSymbolAddress((void**)&Wih, g_Wih); cudaGetSymbolAddress((void**)&Wil, g_Wil);
    cudaGetSymbolAddress((void**)&W1h, g_W1h); cudaGetSymbolAddress((void**)&W1l, g_W1l);
    cudaGetSymbolAddress((void**)&W2h, g_W2h); cudaGetSymbolAddress((void**)&W2l, g_W2l);
    cudaGetSymbolAddress((void**)&W3h, g_W3h); cudaGetSymbolAddress((void**)&W3l, g_W3l);
    cudaGetSymbolAddress((void**)&Woh, g_Woh); cudaGetSymbolAddress((void**)&Wol, g_Wol);

    // lazy-create side streams + events (first call is outside graph capture)
    static cudaStream_t s2 = nullptr, s3 = nullptr;
    static cudaEvent_t evF = nullptr, evJ = nullptr, evW = nullptr;
    if (s2 == nullptr) {
        cudaStreamCreateWithFlags(&s2, cudaStreamNonBlocking);
        cudaStreamCreateWithFlags(&s3, cudaStreamNonBlocking);
        cudaEventCreateWithFlags(&evF, cudaEventDisableTiming);
        cudaEventCreateWithFlags(&evJ, cudaEventDisableTiming);
        cudaEventCreateWithFlags(&evW, cudaEventDisableTiming);
    }

    // ---- fork point ----
    cudaEventRecord(evF, 0);
    cudaStreamWaitEvent(s2, evF, 0);
    cudaStreamWaitEvent(s3, evF, 0);

    // ---- s3: weight splits (DRAM-bound; overlap with tensor-bound gram) ----
    split4_kernel<<<(XDIM * HID / 4 + 1023) / 1024, 256, 0, s3>>>(Win, Wih, Wil, XDIM * HID / 4);
    split4_kernel<<<(HID * HID / 4 + 1023) / 1024, 256, 0, s3>>>(W1, W1h, W1l, HID * HID / 4);
    split4_kernel<<<(HID * HID / 4 + 1023) / 1024, 256, 0, s3>>>(W2, W2h, W2l, HID * HID / 4);
    split4_kernel<<<(HID * HID / 4 + 1023) / 1024, 256, 0, s3>>>(W3, W3h, W3l, HID * HID / 4);
    split4_kernel<<<(HID * DR / 4 + 1023) / 1024, 256, 0, s3>>>(Wout, Woh, Wol, HID * DR / 4);
    cudaEventRecord(evW, s3);

    // ---- default: prep needed by the gram chain ----
    sq_kernel<<<NN / 8, 256>>>(cond, sq);
    split4_kernel<<<(NN * DF / 4 + 1023) / 1024, 256>>>(cond, ch, cl, NN * DF / 4);
    tsplit_kernel<<<(DF * NN + 255) / 256, 256>>>(cond, cth, ctl);

    // ---- fork: gram -> topk -> rescore on s2 ----
    cudaEventRecord(evF, 0);
    cudaStreamWaitEvent(s2, evF, 0);
    mma_gemm<128, 2><<<dim3(NN / 128, NN / 128), 256, 0, s2>>>(
        ch, cl, cth, ctl, sq, nullptr, key, nullptr, nullptr, NN, NN, DF);
    topk_kernel<<<NN / 8, 256, 0, s2>>>(key, cand);
    rescore_kernel<<<NN / 8, 256, 0, s2>>>(cond, sq, cand, nidx);
    cudaEventRecord(evJ, s2);

    // ---- default: MLP chain ----
    concat_split_kernel<<<(NN * XDIM + 255) / 256, 256>>>(cond, tens, x0h, x0l);
    cudaStreamWaitEvent(0, evW, 0);

    mma_gemm<128, 0><<<dim3(HID / 128, NN / 128), 256>>>(
        x0h, x0l, Wih, Wil, b_in, nullptr, nullptr, hAh, hAl, NN, HID, XDIM);
    mma_gemm<128, 0><<<dim3(HID / 128, NN / 128), 256>>>(
        hAh, hAl, W1h, W1l, b1, nullptr, nullptr, hBh, hBl, NN, HID, HID);
    mma_gemm<128, 0><<<dim3(HID / 128, NN / 128), 256>>>(
        hBh, hBl, W2h, W2l, b2, nullptr, nullptr, hAh, hAl, NN, HID, HID);
    mma_gemm<128, 0><<<dim3(HID / 128, NN / 128), 256>>>(
        hAh, hAl, W3h, W3l, b3, nullptr, nullptr, hBh, hBl, NN, HID, HID);

    mma_gemm<64, 1><<<dim3(DR / 64, NN / 128), 128>>>(
        hBh, hBl, Woh, Wol, bout, tens, pushed, nullptr, nullptr, NN, DR, HID);

    // ---- join, then gather ----
    cudaStreamWaitEvent(0, evJ, 0);
    gather_kernel<<<(NN * TOPK * 16 + 255) / 256, 256>>>(nidx, pushed, out);
}